// round 11
// baseline (speedup 1.0000x reference)
#include <cuda_runtime.h>
#include <math.h>
#include <stdint.h>

#define MM 5000
#define EE 128
#define DD 512
#define DII 2048
#define CC 256
#define SS 32
#define BB 32
#define TT 64
#define TMS 63
#define LP 1954
#define LNN 2017
#define NCTA 128

// ---------------- device state ----------------
__device__ int   g_cand[CC];
__device__ float g_At[EE * CC];
__device__ float g_Bm[MM * EE];
__device__ int   g_nlist[MM * SS];
__device__ float g_nprob[MM * SS];

__device__ float g_md[BB * DD];
__device__ float g_q[BB * DD];
__device__ float g_kcache[BB * TMS * DD];
__device__ float g_vcache[BB * TMS * DD];
__device__ float g_ctx[BB * DD];
__device__ float g_x1r[BB * DD];
__device__ float g_x1n[BB * DD];
__device__ float g_h1[BB * DII];
__device__ float g_intr[BB * DD];
__device__ float g_p1[64 * BB * 2];
__device__ float g_p2[64 * BB * 2];
__device__ float g_prob[BB * LP];
__device__ int   g_candl[BB * LP];
__device__ float g_nrecl[BB * LNN];
__device__ int   g_lm[BB];
__device__ float g_ltm[BB];
__device__ int   g_chosen[BB];

__device__ int          g_bar_count = 0;
__device__ volatile int g_bar_gen   = 0;

__device__ __forceinline__ void gridBarrier() {
    __syncthreads();
    if (threadIdx.x == 0) {
        int gen = g_bar_gen;
        __threadfence();
        if (atomicAdd(&g_bar_count, 1) == NCTA - 1) {
            atomicExch(&g_bar_count, 0);
            __threadfence();
            g_bar_gen = gen + 1;
        } else {
            while (g_bar_gen == gen) __nanosleep(64);
        }
        __threadfence();
    }
    __syncthreads();
}

__device__ __forceinline__ void fma4(float4& a, float s, const float4& b) {
    a.x += s * b.x; a.y += s * b.y; a.z += s * b.z; a.w += s * b.w;
}
__device__ __forceinline__ void add4(float4& a, const float4& b) {
    a.x += b.x; a.y += b.y; a.z += b.z; a.w += b.w;
}

// ---------------- threefry (JAX partitionable) ----------------
__device__ __forceinline__ void tf2x32(uint32_t k0, uint32_t k1, uint32_t x0, uint32_t x1,
                                       uint32_t& o0, uint32_t& o1) {
    uint32_t k2 = k0 ^ k1 ^ 0x1BD11BDAu;
    x0 += k0; x1 += k1;
#define TF_R(r) { x0 += x1; x1 = (x1 << r) | (x1 >> (32 - r)); x1 ^= x0; }
    TF_R(13) TF_R(15) TF_R(26) TF_R(6)   x0 += k1; x1 += k2 + 1u;
    TF_R(17) TF_R(29) TF_R(16) TF_R(24)  x0 += k2; x1 += k0 + 2u;
    TF_R(13) TF_R(15) TF_R(26) TF_R(6)   x0 += k0; x1 += k1 + 3u;
    TF_R(17) TF_R(29) TF_R(16) TF_R(24)  x0 += k1; x1 += k2 + 4u;
    TF_R(13) TF_R(15) TF_R(26) TF_R(6)   x0 += k2; x1 += k0 + 5u;
#undef TF_R
    o0 = x0; o1 = x1;
}
__device__ __forceinline__ uint32_t rbits(uint32_t k0, uint32_t k1, uint32_t idx) {
    uint32_t a, b; tf2x32(k0, k1, 0u, idx, a, b); return a ^ b;
}
__device__ __forceinline__ float gumbel_u32(uint32_t bits) {
    const float tiny = 1.17549435e-38f;
    float f = __uint_as_float((bits >> 9) | 0x3f800000u) - 1.0f;
    float u = fmaxf(tiny, f + tiny);
    return -logf(-logf(u));
}

// ---------------- reductions ----------------
__device__ __forceinline__ float blockSum(float v, float* rs) {
    int tid = threadIdx.x, w = tid >> 5, l = tid & 31, nw = blockDim.x >> 5;
#pragma unroll
    for (int o = 16; o > 0; o >>= 1) v += __shfl_xor_sync(~0u, v, o);
    if (l == 0) rs[w] = v;
    __syncthreads();
    if (w == 0) {
        float x = (l < nw) ? rs[l] : 0.0f;
#pragma unroll
        for (int o = 16; o > 0; o >>= 1) x += __shfl_xor_sync(~0u, x, o);
        if (l == 0) rs[0] = x;
    }
    __syncthreads();
    float r = rs[0]; __syncthreads(); return r;
}
__device__ __forceinline__ float blockMax(float v, float* rs) {
    int tid = threadIdx.x, w = tid >> 5, l = tid & 31, nw = blockDim.x >> 5;
#pragma unroll
    for (int o = 16; o > 0; o >>= 1) v = fmaxf(v, __shfl_xor_sync(~0u, v, o));
    if (l == 0) rs[w] = v;
    __syncthreads();
    if (w == 0) {
        float x = (l < nw) ? rs[l] : -INFINITY;
#pragma unroll
        for (int o = 16; o > 0; o >>= 1) x = fmaxf(x, __shfl_xor_sync(~0u, x, o));
        if (l == 0) rs[0] = x;
    }
    __syncthreads();
    float r = rs[0]; __syncthreads(); return r;
}
__device__ __forceinline__ void warpArgmax(float& v, int& idx) {
#pragma unroll
    for (int o = 16; o > 0; o >>= 1) {
        float ov = __shfl_xor_sync(~0u, v, o);
        int   oi = __shfl_xor_sync(~0u, idx, o);
        if (ov > v || (ov == v && oi < idx)) { v = ov; idx = oi; }
    }
}
__device__ __forceinline__ void blockArgmax(float& v, int& idx, float* rv, int* ri) {
    int tid = threadIdx.x, w = tid >> 5, l = tid & 31, nw = (blockDim.x + 31) >> 5;
    warpArgmax(v, idx);
    if (l == 0) { rv[w] = v; ri[w] = idx; }
    __syncthreads();
    if (w == 0) {
        float vv = (l < nw) ? rv[l] : -INFINITY;
        int   ii = (l < nw) ? ri[l] : 0x7fffffff;
        warpArgmax(vv, ii);
        if (l == 0) { rv[0] = vv; ri[0] = ii; }
    }
    __syncthreads();
    v = rv[0]; idx = ri[0]; __syncthreads();
}

// ---------------- precompute ----------------
__global__ void __launch_bounds__(1024) k_topk_cand() {
    __shared__ float vals[MM];
    __shared__ float rv[32]; __shared__ int ri[32];
    uint32_t ka, kb; tf2x32(0u, 7u, 0u, 0u, ka, kb);
    for (int i = threadIdx.x; i < MM; i += blockDim.x)
        vals[i] = gumbel_u32(rbits(ka, kb, (uint32_t)i));
    __syncthreads();
    for (int r = 0; r < CC; r++) {
        float bv = -INFINITY; int bi = 0x7fffffff;
        for (int i = threadIdx.x; i < MM; i += blockDim.x) {
            float v = vals[i];
            if (v > bv) { bv = v; bi = i; }
        }
        blockArgmax(bv, bi, rv, ri);
        if (threadIdx.x == 0) { g_cand[r] = bi; vals[bi] = -INFINITY; }
        __syncthreads();
    }
}

__global__ void __launch_bounds__(EE) k_bm(const float* __restrict__ emb,
                                           const float* __restrict__ s1w) {
    __shared__ float se[EE];
    int m = blockIdx.x, d = threadIdx.x;
    se[d] = emb[m * EE + d];
    __syncthreads();
    float acc = 0.0f;
#pragma unroll 8
    for (int e = 0; e < EE; e++) acc += se[e] * s1w[(EE + e) * EE + d];
    g_Bm[m * EE + d] = acc;
}

__global__ void __launch_bounds__(EE) k_a(const float* __restrict__ emb,
                                          const float* __restrict__ s1w) {
    __shared__ float se[EE];
    int c = blockIdx.x, d = threadIdx.x;
    se[d] = emb[g_cand[c] * EE + d];
    __syncthreads();
    float acc = 0.0f;
#pragma unroll 8
    for (int e = 0; e < EE; e++) acc += se[e] * s1w[e * EE + d];
    g_At[d * CC + c] = acc;
}

__global__ void __launch_bounds__(CC) k_selectp(const float* __restrict__ s1b,
                                                const float* __restrict__ s2w,
                                                const float* __restrict__ s2b) {
    __shared__ float sb[EE], sw[EE], sbm[EE];
    __shared__ float p[CC], sc[CC];
    __shared__ float rs[32], rv[32]; __shared__ int ri[32];
    int m = blockIdx.x, c = threadIdx.x;
    if (c < EE) { sb[c] = s1b[c]; sw[c] = s2w[c]; sbm[c] = g_Bm[m * EE + c]; }
    __syncthreads();
    float acc = 0.0f;
#pragma unroll 4
    for (int e = 0; e < EE; e++) {
        float t = g_At[e * CC + c] + sbm[e] + sb[e];
        t = (t >= 0.0f) ? t : 0.01f * t;
        acc += t * sw[e];
    }
    float logit = acc + s2b[0];
    float mx = blockMax(logit, rs);
    float ex = expf(logit - mx);
    float sm = blockSum(ex, rs);
    float pc = ex / sm;
    p[c] = pc;
    uint32_t ka, kb; tf2x32(0u, 7u, 0u, 1u, ka, kb);
    sc[c] = logf(pc) + gumbel_u32(rbits(ka, kb, (uint32_t)(m * CC + c)));
    __syncthreads();
    for (int s = 0; s < SS; s++) {
        float bv = sc[c]; int bi = c;
        blockArgmax(bv, bi, rv, ri);
        if (threadIdx.x == 0) {
            g_nlist[m * SS + s] = g_cand[bi];
            g_nprob[m * SS + s] = p[bi];
            sc[bi] = -INFINITY;
        }
        __syncthreads();
    }
}

// ---------------- per-row md GEMV (256 threads) ----------------
__device__ void md_from_state(int r, int nm, float nt, const float* emb,
                              const float* te_w, const float* te_b,
                              const float* el_w, const float* el_b, float* vv) {
    int t = threadIdx.x;
    if (t < EE) vv[t] = emb[nm * EE + t] + 0.1f * (nt * te_w[t] + te_b[t]);
    __syncthreads();
    for (int c = t; c < DD; c += 256) {
        float acc = el_b[c];
#pragma unroll 8
        for (int k = 0; k < EE; k++) acc += vv[k] * el_w[k * DD + c];
        g_md[r * DD + c] = (acc >= 0.f) ? acc : 0.01f * acc;
    }
    __syncthreads();
}

// ---------------- the persistent fused scan kernel ----------------
__global__ void __launch_bounds__(256) p_main(
    const int* __restrict__ marker, const float* __restrict__ timed,
    const float* __restrict__ maskd, const float* __restrict__ emb,
    const float* __restrict__ te_w, const float* __restrict__ te_b,
    const float* __restrict__ el_w, const float* __restrict__ el_b,
    const float* __restrict__ ml_w, const float* __restrict__ ml_b,
    const float* __restrict__ tl_w, const float* __restrict__ tl_b,
    const float* __restrict__ wq, const float* __restrict__ wk,
    const float* __restrict__ wv, const float* __restrict__ wo,
    const float* __restrict__ wo_b,
    const float* __restrict__ ln1s, const float* __restrict__ ln1b,
    const float* __restrict__ ff1w, const float* __restrict__ ff1b,
    const float* __restrict__ ff2w, const float* __restrict__ ff2b,
    const float* __restrict__ ln2s, const float* __restrict__ ln2b,
    float* __restrict__ out)
{
    extern __shared__ float xt[];          // 512*33 floats
    __shared__ float4 scr[512];
    __shared__ float redA[256], redB[256];
    __shared__ float mean[32], rstd[32];
    __shared__ float sint[DD];
    __shared__ float sq[64], ssc[64];
    __shared__ float smw[SS]; __shared__ int snb[SS];
    __shared__ float rs[32], rv[32]; __shared__ int ri[32];
    __shared__ float vv[EE];

    const int cta = blockIdx.x, t = threadIdx.x;

    // ---- init phase (CTAs 0..31, one per row) ----
    if (cta < BB) {
        int r = cta;
        for (int j = t; j < LP; j += 256) { g_prob[r * LP + j] = 0.f; g_candl[r * LP + j] = 0; }
        for (int j = t; j < LNN; j += 256) g_nrecl[r * LNN + j] = 0.f;
        int m0 = marker[r * TT]; float t0 = timed[r * TT];
        if (t == 0) {
            g_prob[r * LP] = 1.f; g_candl[r * LP] = m0; g_nrecl[r * LNN] = 1.f;
            g_lm[r] = m0; g_ltm[r] = t0; g_chosen[r] = 0;
            out[0 * (BB * TT) + r * TT] = (float)m0;
            out[1 * (BB * TT) + r * TT] = t0;
            out[2 * (BB * TT) + r * TT] = maskd[r * TT];
            out[3 * (BB * TT) + r * TT] = 1.f;
            out[4 * (BB * TT) + r * TT] = 1.f;
        }
        __syncthreads();
        md_from_state(r, m0, t0, emb, te_w, te_b, el_w, el_b, vv);
    }
    gridBarrier();

    for (int i = 0; i < TMS; i++) {
        // ---- phase qkv (CTAs 0..95): [32 rows x 16 cols] of one of wq/wk/wv ----
        if (cta < 96) {
            int m = cta >> 5, cb = (cta & 31) * 16;
            const float* W = (m == 0) ? wq : (m == 1) ? wk : wv;
            for (int f = t; f < 4096; f += 256) {
                int r = f >> 7, k4 = f & 127;
                float4 v = ((const float4*)g_md)[f];
                xt[(4 * k4 + 0) * 33 + r] = v.x; xt[(4 * k4 + 1) * 33 + r] = v.y;
                xt[(4 * k4 + 2) * 33 + r] = v.z; xt[(4 * k4 + 3) * 33 + r] = v.w;
            }
            __syncthreads();
            int p = t >> 6, g = (t >> 4) & 3, rp = t & 15;
            const float4* W4 = (const float4*)W + (cb >> 2) + g;
            float4 a0 = make_float4(0, 0, 0, 0), a1 = a0;
            int k = p * 128;
#pragma unroll 8
            for (int kk = 0; kk < 128; kk++, k++) {
                float4 w4 = W4[(size_t)k * 128];
                fma4(a0, xt[k * 33 + rp], w4);
                fma4(a1, xt[k * 33 + rp + 16], w4);
            }
            scr[((p * 2 + 0) * 16 + rp) * 4 + g] = a0;
            scr[((p * 2 + 1) * 16 + rp) * 4 + g] = a1;
            __syncthreads();
            if (t < 128) {
                int r = t & 31, gg = t >> 5;
                int rp2 = r & 15, h = r >> 4;
                float4 a = scr[(h * 16 + rp2) * 4 + gg];
#pragma unroll
                for (int pp = 1; pp < 4; pp++)
                    add4(a, scr[((pp * 2 + h) * 16 + rp2) * 4 + gg]);
                int c4 = (cb >> 2) + gg;
                if (m == 0)      ((float4*)g_q)[r * 128 + c4] = a;
                else if (m == 1) ((float4*)g_kcache)[(size_t)(r * TMS + i) * 128 + c4] = a;
                else             ((float4*)g_vcache)[(size_t)(r * TMS + i) * 128 + c4] = a;
            }
            __syncthreads();
        }
        gridBarrier();

        // ---- phase attn: 2 (row,head) units per CTA ----
#pragma unroll
        for (int u = 0; u < 2; u++) {
            int unit = cta * 2 + u;
            int r = unit >> 3, h = unit & 7;
            if (t < 64) sq[t] = g_q[r * DD + h * 64 + t];
            __syncthreads();
            if (t <= i) {
                const float* kp = &g_kcache[(size_t)(r * TMS + t) * DD + h * 64];
                float acc = 0.f;
#pragma unroll 8
                for (int d = 0; d < 64; d++) acc += sq[d] * kp[d];
                ssc[t] = acc * 0.125f;
            }
            __syncthreads();
            if (t == 0) {
                float mx = -INFINITY;
                for (int tt = 0; tt <= i; tt++) mx = fmaxf(mx, ssc[tt]);
                float sm = 0.f;
                for (int tt = 0; tt <= i; tt++) { float e = expf(ssc[tt] - mx); ssc[tt] = e; sm += e; }
                for (int tt = 0; tt <= i; tt++) ssc[tt] /= sm;
            }
            __syncthreads();
            if (t < 64) {
                float acc = 0.f;
                for (int tt = 0; tt <= i; tt++)
                    acc += ssc[tt] * g_vcache[(size_t)(r * TMS + tt) * DD + h * 64 + t];
                g_ctx[r * DD + h * 64 + t] = acc;
            }
            __syncthreads();
        }
        gridBarrier();

        // ---- phase wo (CTAs 0..63): [32 rows x 8 cols], K=512 ----
        if (cta < 64) {
            int j = cta;
            int r = t & 31, p = t >> 5;
            const float4* W4 = (const float4*)wo + j * 2;
            const float4* X4 = (const float4*)g_ctx + r * 128 + p * 16;
            float4 a0 = make_float4(0, 0, 0, 0), a1 = a0;
            int kb = p * 64;
#pragma unroll 4
            for (int f = 0; f < 16; f++) {
                float4 x = X4[f];
                int k = kb + 4 * f;
                fma4(a0, x.x, W4[(size_t)(k+0)*128]); fma4(a1, x.x, W4[(size_t)(k+0)*128+1]);
                fma4(a0, x.y, W4[(size_t)(k+1)*128]); fma4(a1, x.y, W4[(size_t)(k+1)*128+1]);
                fma4(a0, x.z, W4[(size_t)(k+2)*128]); fma4(a1, x.z, W4[(size_t)(k+2)*128+1]);
                fma4(a0, x.w, W4[(size_t)(k+3)*128]); fma4(a1, x.w, W4[(size_t)(k+3)*128+1]);
            }
            scr[(p * 32 + r) * 2 + 0] = a0;
            scr[(p * 32 + r) * 2 + 1] = a1;
            __syncthreads();
            if (t < 32) {
                float4 A = scr[t * 2], B = scr[t * 2 + 1];
#pragma unroll
                for (int pp = 1; pp < 8; pp++) {
                    add4(A, scr[(pp * 32 + t) * 2]);
                    add4(B, scr[(pp * 32 + t) * 2 + 1]);
                }
                float4 m0 = ((const float4*)g_md)[t * 128 + j * 2];
                float4 m1 = ((const float4*)g_md)[t * 128 + j * 2 + 1];
                float4 b0 = ((const float4*)wo_b)[j * 2];
                float4 b1 = ((const float4*)wo_b)[j * 2 + 1];
                float4 v0, v1;
                v0.x = m0.x + A.x + b0.x; v0.y = m0.y + A.y + b0.y;
                v0.z = m0.z + A.z + b0.z; v0.w = m0.w + A.w + b0.w;
                v1.x = m1.x + B.x + b1.x; v1.y = m1.y + B.y + b1.y;
                v1.z = m1.z + B.z + b1.z; v1.w = m1.w + B.w + b1.w;
                ((float4*)g_x1r)[t * 128 + j * 2] = v0;
                ((float4*)g_x1r)[t * 128 + j * 2 + 1] = v1;
                float s1 = v0.x + v0.y + v0.z + v0.w + v1.x + v1.y + v1.z + v1.w;
                float s2 = v0.x*v0.x + v0.y*v0.y + v0.z*v0.z + v0.w*v0.w
                         + v1.x*v1.x + v1.y*v1.y + v1.z*v1.z + v1.w*v1.w;
                g_p1[(j * 32 + t) * 2] = s1;
                g_p1[(j * 32 + t) * 2 + 1] = s2;
            }
            __syncthreads();
        }
        gridBarrier();

        // ---- phase ff1 (all 128 CTAs): LN1 + [32 rows x 16 cols of 2048], K=512 ----
        {
            int j = cta;
            {
                int rr = t & 31, pp = t >> 5;
                float s1 = 0.f, s2 = 0.f;
                for (int q = pp * 8; q < pp * 8 + 8; q++) {
                    s1 += g_p1[(q * 32 + rr) * 2];
                    s2 += g_p1[(q * 32 + rr) * 2 + 1];
                }
                redA[t] = s1; redB[t] = s2;
                __syncthreads();
                if (t < 32) {
                    float S1 = 0.f, S2 = 0.f;
#pragma unroll
                    for (int pp2 = 0; pp2 < 8; pp2++) { S1 += redA[pp2 * 32 + t]; S2 += redB[pp2 * 32 + t]; }
                    float m = S1 / (float)DD;
                    float var = fmaxf(S2 / (float)DD - m * m, 0.f);
                    mean[t] = m; rstd[t] = 1.f / sqrtf(var + 1e-5f);
                }
                __syncthreads();
            }
            for (int idx = t; idx < 16384; idx += 256) {
                int r = idx >> 9, c = idx & 511;
                float v = (g_x1r[r * DD + c] - mean[r]) * rstd[r] * ln1s[c] + ln1b[c];
                xt[c * 33 + r] = v;
            }
            __syncthreads();
            if (j < 32) {
                for (int idx = t; idx < 512; idx += 256) {
                    int rr = idx & 31, cc = j * 16 + (idx >> 5);
                    g_x1n[rr * DD + cc] = xt[cc * 33 + rr];
                }
            }
            int cb = j * 16;
            int p = t >> 6, g = (t >> 4) & 3, rp = t & 15;
            const float4* W4 = (const float4*)ff1w + (cb >> 2) + g;
            float4 a0 = make_float4(0, 0, 0, 0), a1 = a0;
            int k = p * 128;
#pragma unroll 8
            for (int kk = 0; kk < 128; kk++, k++) {
                float4 w4 = W4[(size_t)k * 512];
                fma4(a0, xt[k * 33 + rp], w4);
                fma4(a1, xt[k * 33 + rp + 16], w4);
            }
            scr[((p * 2 + 0) * 16 + rp) * 4 + g] = a0;
            scr[((p * 2 + 1) * 16 + rp) * 4 + g] = a1;
            __syncthreads();
            if (t < 128) {
                int r = t & 31, gg = t >> 5;
                int rp2 = r & 15, h = r >> 4;
                float4 a = scr[(h * 16 + rp2) * 4 + gg];
#pragma unroll
                for (int pp = 1; pp < 4; pp++)
                    add4(a, scr[((pp * 2 + h) * 16 + rp2) * 4 + gg]);
                float4 b4 = ((const float4*)ff1b)[(cb >> 2) + gg];
                a.x = fmaxf(a.x + b4.x, 0.f); a.y = fmaxf(a.y + b4.y, 0.f);
                a.z = fmaxf(a.z + b4.z, 0.f); a.w = fmaxf(a.w + b4.w, 0.f);
                ((float4*)g_h1)[r * 512 + (cb >> 2) + gg] = a;
            }
            __syncthreads();
        }
        gridBarrier();

        // ---- phase ff2 (CTAs 0..63): [32 rows x 8 cols], K=2048 ----
        if (cta < 64) {
            int j = cta;
            int r = t & 31, p = t >> 5;
            const float4* W4 = (const float4*)ff2w + j * 2;
            const float4* X4 = (const float4*)g_h1 + r * 512 + p * 64;
            float4 a0 = make_float4(0, 0, 0, 0), a1 = a0;
            int kb = p * 256;
#pragma unroll 4
            for (int f = 0; f < 64; f++) {
                float4 x = X4[f];
                int k = kb + 4 * f;
                fma4(a0, x.x, W4[(size_t)(k+0)*128]); fma4(a1, x.x, W4[(size_t)(k+0)*128+1]);
                fma4(a0, x.y, W4[(size_t)(k+1)*128]); fma4(a1, x.y, W4[(size_t)(k+1)*128+1]);
                fma4(a0, x.z, W4[(size_t)(k+2)*128]); fma4(a1, x.z, W4[(size_t)(k+2)*128+1]);
                fma4(a0, x.w, W4[(size_t)(k+3)*128]); fma4(a1, x.w, W4[(size_t)(k+3)*128+1]);
            }
            scr[(p * 32 + r) * 2 + 0] = a0;
            scr[(p * 32 + r) * 2 + 1] = a1;
            __syncthreads();
            if (t < 32) {
                float4 A = scr[t * 2], B = scr[t * 2 + 1];
#pragma unroll
                for (int pp = 1; pp < 8; pp++) {
                    add4(A, scr[(pp * 32 + t) * 2]);
                    add4(B, scr[(pp * 32 + t) * 2 + 1]);
                }
                float4 x0 = ((const float4*)g_x1n)[t * 128 + j * 2];
                float4 x1 = ((const float4*)g_x1n)[t * 128 + j * 2 + 1];
                float4 b0 = ((const float4*)ff2b)[j * 2];
                float4 b1 = ((const float4*)ff2b)[j * 2 + 1];
                float4 v0, v1;
                v0.x = x0.x + A.x + b0.x; v0.y = x0.y + A.y + b0.y;
                v0.z = x0.z + A.z + b0.z; v0.w = x0.w + A.w + b0.w;
                v1.x = x1.x + B.x + b1.x; v1.y = x1.y + B.y + b1.y;
                v1.z = x1.z + B.z + b1.z; v1.w = x1.w + B.w + b1.w;
                ((float4*)g_intr)[t * 128 + j * 2] = v0;
                ((float4*)g_intr)[t * 128 + j * 2 + 1] = v1;
                float s1 = v0.x + v0.y + v0.z + v0.w + v1.x + v1.y + v1.z + v1.w;
                float s2 = v0.x*v0.x + v0.y*v0.y + v0.z*v0.z + v0.w*v0.w
                         + v1.x*v1.x + v1.y*v1.y + v1.z*v1.z + v1.w*v1.w;
                g_p2[(j * 32 + t) * 2] = s1;
                g_p2[(j * 32 + t) * 2 + 1] = s2;
            }
            __syncthreads();
        }
        gridBarrier();

        // ---- phase select (CTAs 0..31): LN2 + sampling + next md ----
        if (cta < BB) {
            int r = cta;
            int lm = g_lm[r]; float lt = g_ltm[r]; int chosen = g_chosen[r];

            float s1 = (t < 64) ? g_p2[(t * 32 + r) * 2] : 0.f;
            float s2 = (t < 64) ? g_p2[(t * 32 + r) * 2 + 1] : 0.f;
            float S1 = blockSum(s1, rs);
            float S2 = blockSum(s2, rs);
            float mn = S1 / (float)DD;
            float var = fmaxf(S2 / (float)DD - mn * mn, 0.f);
            float rsd = 1.f / sqrtf(var + 1e-5f);
            for (int c = t; c < DD; c += 256)
                sint[c] = (g_intr[r * DD + c] - mn) * rsd * ln2s[c] + ln2b[c];
            __syncthreads();

            float tv = 0.f, mv = 0.f;
            for (int c = t; c < DD; c += 256) {
                tv += sint[c] * tl_w[c];
                mv += sint[c] * ml_w[EE + c];
            }
            float tdot = blockSum(tv, rs) + tl_b[0];
            float iml = blockSum(mv, rs);
            float nt = lt + (fmaxf(tdot, 0.f) + log1pf(expf(-fabsf(tdot))));

            if (t < SS) {
                snb[t] = g_nlist[lm * SS + t];
                g_nrecl[r * LNN + 1 + i * SS + t] = g_nprob[lm * SS + t];
            }
            __syncthreads();
            if (t < SS) {
                float acc = 0.f;
                const float4* ep = (const float4*)&emb[snb[t] * EE];
                const float4* mw4 = (const float4*)ml_w;
#pragma unroll
                for (int e = 0; e < 32; e++) {
                    float4 a4 = ep[e], w4 = mw4[e];
                    acc += a4.x * w4.x + a4.y * w4.y + a4.z * w4.z + a4.w * w4.w;
                }
                smw[t] = acc + iml + ml_b[0];
            }
            __syncthreads();
            if (t < SS) {
                float v = smw[t];
                float mx = v;
#pragma unroll
                for (int o = 16; o > 0; o >>= 1) mx = fmaxf(mx, __shfl_xor_sync(~0u, mx, o));
                float ex = expf(v - mx);
                float sm = ex;
#pragma unroll
                for (int o = 16; o > 0; o >>= 1) sm += __shfl_xor_sync(~0u, sm, o);
                float mp = ex / sm;
                float pc = g_prob[r * LP + chosen];
                __syncwarp();
                float att = pc * mp;
                if (t == 0) g_prob[r * LP + chosen] = att;
                else {
                    g_prob[r * LP + 1 + i * (SS - 1) + t - 1] = att;
                    g_candl[r * LP + 1 + i * (SS - 1) + t - 1] = snb[t];
                }
            }
            __syncthreads();

            uint32_t ka, kb;
            tf2x32(0u, 11u, 0u, (uint32_t)i, ka, kb);
            float bv = -INFINITY; int bi = 0x7fffffff;
            for (int jj = t; jj < LP; jj += 256) {
                float z = logf(g_prob[r * LP + jj]) + gumbel_u32(rbits(ka, kb, (uint32_t)(r * LP + jj)));
                if (z > bv) { bv = z; bi = jj; }
            }
            blockArgmax(bv, bi, rv, ri);
            int nc = bi;
            int nm = g_candl[r * LP + nc];
            if (t == 0) {
                g_chosen[r] = nc; g_lm[r] = nm; g_ltm[r] = nt;
                int o = r * TT + (i + 1);
                out[0 * (BB * TT) + o] = (float)nm;
                out[1 * (BB * TT) + o] = nt;
                out[2 * (BB * TT) + o] = (nt < 50.0f) ? 1.0f : 0.0f;
                out[3 * (BB * TT) + o] = g_nrecl[r * LNN + nc];
                out[4 * (BB * TT) + o] = g_prob[r * LP + nc];
            }
            __syncthreads();
            md_from_state(r, nm, nt, emb, te_w, te_b, el_w, el_b, vv);
        }
        gridBarrier();
    }
}

extern "C" void kernel_launch(void* const* d_in, const int* in_sizes, int n_in,
                              void* d_out, int out_size) {
    const int*   marker = (const int*)  d_in[0];
    const float* timed  = (const float*)d_in[1];
    const float* maskd  = (const float*)d_in[2];
    const float* emb    = (const float*)d_in[3];
    const float* te_w   = (const float*)d_in[4];
    const float* te_b   = (const float*)d_in[5];
    const float* el_w   = (const float*)d_in[6];
    const float* el_b   = (const float*)d_in[7];
    const float* s1_w   = (const float*)d_in[8];
    const float* s1_b   = (const float*)d_in[9];
    const float* s2_w   = (const float*)d_in[10];
    const float* s2_b   = (const float*)d_in[11];
    const float* ml_w   = (const float*)d_in[12];
    const float* ml_b   = (const float*)d_in[13];
    const float* tl_w   = (const float*)d_in[14];
    const float* tl_b   = (const float*)d_in[15];
    const float* wq     = (const float*)d_in[16];
    const float* wk     = (const float*)d_in[17];
    const float* wv     = (const float*)d_in[18];
    const float* wo     = (const float*)d_in[19];
    const float* wo_b   = (const float*)d_in[20];
    const float* ln1_s  = (const float*)d_in[21];
    const float* ln1_b  = (const float*)d_in[22];
    const float* ff1_w  = (const float*)d_in[23];
    const float* ff1_b  = (const float*)d_in[24];
    const float* ff2_w  = (const float*)d_in[25];
    const float* ff2_b  = (const float*)d_in[26];
    const float* ln2_s  = (const float*)d_in[27];
    const float* ln2_b  = (const float*)d_in[28];
    float* out = (float*)d_out;

    static int inited = 0;
    if (!inited) {
        cudaFuncSetAttribute(p_main, cudaFuncAttributeMaxDynamicSharedMemorySize,
                             512 * 33 * 4);
        inited = 1;
    }

    k_topk_cand<<<1, 1024>>>();
    k_bm<<<MM, EE>>>(emb, s1_w);
    k_a<<<CC, EE>>>(emb, s1_w);
    k_selectp<<<MM, CC>>>(s1_b, s2_w, s2_b);
    p_main<<<NCTA, 256, 512 * 33 * 4>>>(
        marker, timed, maskd, emb, te_w, te_b, el_w, el_b, ml_w, ml_b,
        tl_w, tl_b, wq, wk, wv, wo, wo_b, ln1_s, ln1_b,
        ff1_w, ff1_b, ff2_w, ff2_b, ln2_s, ln2_b, out);
}

// round 12
// speedup vs baseline: 1.6647x; 1.6647x over previous
#include <cuda_runtime.h>
#include <math.h>
#include <stdint.h>

#define MM 5000
#define EE 128
#define DD 512
#define DII 2048
#define CC 256
#define SS 32
#define BB 32
#define TT 64
#define TMS 63
#define LP 1954
#define LNN 2017

#define DYN_FLOATS (4096 + 2048 + 512 + 512 + 512 + 512 + 256 + 256 + 128 + LP + LNN + LP)
#define DYN_BYTES (DYN_FLOATS * 4)

// ---------------- device state ----------------
__device__ int   g_cand[CC];
__device__ float g_At[EE * CC];
__device__ float g_Bm[MM * EE];
__device__ int   g_nlist[MM * SS];
__device__ float g_nprob[MM * SS];

__device__ float g_md[BB * DD];
__device__ float g_kc[BB * TMS * DD];
__device__ float g_vc[BB * TMS * DD];
__device__ float g_ctx[BB * DD];
__device__ float g_x1r[BB * DD];
__device__ float g_h1[BB * DII];
__device__ float g_intr[BB * DD];
__device__ float g_st1[BB * 8];
__device__ float g_st2[BB * 8];
__device__ int   g_lm[BB];
__device__ float g_ltm[BB];

__device__ int          g_rcnt[BB * 32];
__device__ volatile int g_rgen[BB * 32];

__device__ __forceinline__ void rowBarrier(int r) {
    __syncthreads();
    if (threadIdx.x == 0) {
        volatile int* genp = &g_rgen[r * 32];
        int gen = *genp;
        __threadfence();
        if (atomicAdd(&g_rcnt[r * 32], 1) == 1) {
            g_rcnt[r * 32] = 0;
            __threadfence();
            *genp = gen + 1;
        } else {
            while (*genp == gen) { }
        }
        __threadfence();
    }
    __syncthreads();
}

// ---------------- threefry (JAX partitionable) ----------------
__device__ __forceinline__ void tf2x32(uint32_t k0, uint32_t k1, uint32_t x0, uint32_t x1,
                                       uint32_t& o0, uint32_t& o1) {
    uint32_t k2 = k0 ^ k1 ^ 0x1BD11BDAu;
    x0 += k0; x1 += k1;
#define TF_R(r) { x0 += x1; x1 = (x1 << r) | (x1 >> (32 - r)); x1 ^= x0; }
    TF_R(13) TF_R(15) TF_R(26) TF_R(6)   x0 += k1; x1 += k2 + 1u;
    TF_R(17) TF_R(29) TF_R(16) TF_R(24)  x0 += k2; x1 += k0 + 2u;
    TF_R(13) TF_R(15) TF_R(26) TF_R(6)   x0 += k0; x1 += k1 + 3u;
    TF_R(17) TF_R(29) TF_R(16) TF_R(24)  x0 += k1; x1 += k2 + 4u;
    TF_R(13) TF_R(15) TF_R(26) TF_R(6)   x0 += k2; x1 += k0 + 5u;
#undef TF_R
    o0 = x0; o1 = x1;
}
__device__ __forceinline__ uint32_t rbits(uint32_t k0, uint32_t k1, uint32_t idx) {
    uint32_t a, b; tf2x32(k0, k1, 0u, idx, a, b); return a ^ b;
}
__device__ __forceinline__ float gumbel_u32(uint32_t bits) {
    const float tiny = 1.17549435e-38f;
    float f = __uint_as_float((bits >> 9) | 0x3f800000u) - 1.0f;
    float u = fmaxf(tiny, f + tiny);
    return -logf(-logf(u));
}

// ---------------- reductions ----------------
__device__ __forceinline__ float blockSum(float v, float* rs) {
    int tid = threadIdx.x, w = tid >> 5, l = tid & 31, nw = blockDim.x >> 5;
#pragma unroll
    for (int o = 16; o > 0; o >>= 1) v += __shfl_xor_sync(~0u, v, o);
    if (l == 0) rs[w] = v;
    __syncthreads();
    if (w == 0) {
        float x = (l < nw) ? rs[l] : 0.0f;
#pragma unroll
        for (int o = 16; o > 0; o >>= 1) x += __shfl_xor_sync(~0u, x, o);
        if (l == 0) rs[0] = x;
    }
    __syncthreads();
    float r = rs[0]; __syncthreads(); return r;
}
__device__ __forceinline__ float blockMax(float v, float* rs) {
    int tid = threadIdx.x, w = tid >> 5, l = tid & 31, nw = blockDim.x >> 5;
#pragma unroll
    for (int o = 16; o > 0; o >>= 1) v = fmaxf(v, __shfl_xor_sync(~0u, v, o));
    if (l == 0) rs[w] = v;
    __syncthreads();
    if (w == 0) {
        float x = (l < nw) ? rs[l] : -INFINITY;
#pragma unroll
        for (int o = 16; o > 0; o >>= 1) x = fmaxf(x, __shfl_xor_sync(~0u, x, o));
        if (l == 0) rs[0] = x;
    }
    __syncthreads();
    float r = rs[0]; __syncthreads(); return r;
}
__device__ __forceinline__ void warpArgmax(float& v, int& idx) {
#pragma unroll
    for (int o = 16; o > 0; o >>= 1) {
        float ov = __shfl_xor_sync(~0u, v, o);
        int   oi = __shfl_xor_sync(~0u, idx, o);
        if (ov > v || (ov == v && oi < idx)) { v = ov; idx = oi; }
    }
}
__device__ __forceinline__ void blockArgmax(float& v, int& idx, float* rv, int* ri) {
    int tid = threadIdx.x, w = tid >> 5, l = tid & 31, nw = (blockDim.x + 31) >> 5;
    warpArgmax(v, idx);
    if (l == 0) { rv[w] = v; ri[w] = idx; }
    __syncthreads();
    if (w == 0) {
        float vv = (l < nw) ? rv[l] : -INFINITY;
        int   ii = (l < nw) ? ri[l] : 0x7fffffff;
        warpArgmax(vv, ii);
        if (l == 0) { rv[0] = vv; ri[0] = ii; }
    }
    __syncthreads();
    v = rv[0]; idx = ri[0]; __syncthreads();
}

// ---------------- precompute (unchanged, proven) ----------------
__global__ void __launch_bounds__(1024) k_topk_cand() {
    __shared__ float vals[MM];
    __shared__ float rv[32]; __shared__ int ri[32];
    uint32_t ka, kb; tf2x32(0u, 7u, 0u, 0u, ka, kb);
    for (int i = threadIdx.x; i < MM; i += blockDim.x)
        vals[i] = gumbel_u32(rbits(ka, kb, (uint32_t)i));
    __syncthreads();
    for (int r = 0; r < CC; r++) {
        float bv = -INFINITY; int bi = 0x7fffffff;
        for (int i = threadIdx.x; i < MM; i += blockDim.x) {
            float v = vals[i];
            if (v > bv) { bv = v; bi = i; }
        }
        blockArgmax(bv, bi, rv, ri);
        if (threadIdx.x == 0) { g_cand[r] = bi; vals[bi] = -INFINITY; }
        __syncthreads();
    }
}

__global__ void __launch_bounds__(EE) k_bm(const float* __restrict__ emb,
                                           const float* __restrict__ s1w) {
    __shared__ float se[EE];
    int m = blockIdx.x, d = threadIdx.x;
    se[d] = emb[m * EE + d];
    __syncthreads();
    float acc = 0.0f;
#pragma unroll 8
    for (int e = 0; e < EE; e++) acc += se[e] * s1w[(EE + e) * EE + d];
    g_Bm[m * EE + d] = acc;
}

__global__ void __launch_bounds__(EE) k_a(const float* __restrict__ emb,
                                          const float* __restrict__ s1w) {
    __shared__ float se[EE];
    int c = blockIdx.x, d = threadIdx.x;
    se[d] = emb[g_cand[c] * EE + d];
    __syncthreads();
    float acc = 0.0f;
#pragma unroll 8
    for (int e = 0; e < EE; e++) acc += se[e] * s1w[e * EE + d];
    g_At[d * CC + c] = acc;
}

__global__ void __launch_bounds__(CC) k_selectp(const float* __restrict__ s1b,
                                                const float* __restrict__ s2w,
                                                const float* __restrict__ s2b) {
    __shared__ float sb[EE], sw[EE], sbm[EE];
    __shared__ float p[CC], sc[CC];
    __shared__ float rs[32], rv[32]; __shared__ int ri[32];
    int m = blockIdx.x, c = threadIdx.x;
    if (c < EE) { sb[c] = s1b[c]; sw[c] = s2w[c]; sbm[c] = g_Bm[m * EE + c]; }
    __syncthreads();
    float acc = 0.0f;
#pragma unroll 4
    for (int e = 0; e < EE; e++) {
        float t = g_At[e * CC + c] + sbm[e] + sb[e];
        t = (t >= 0.0f) ? t : 0.01f * t;
        acc += t * sw[e];
    }
    float logit = acc + s2b[0];
    float mx = blockMax(logit, rs);
    float ex = expf(logit - mx);
    float sm = blockSum(ex, rs);
    float pc = ex / sm;
    p[c] = pc;
    uint32_t ka, kb; tf2x32(0u, 7u, 0u, 1u, ka, kb);
    sc[c] = logf(pc) + gumbel_u32(rbits(ka, kb, (uint32_t)(m * CC + c)));
    __syncthreads();
    for (int s = 0; s < SS; s++) {
        float bv = sc[c]; int bi = c;
        blockArgmax(bv, bi, rv, ri);
        if (threadIdx.x == 0) {
            g_nlist[m * SS + s] = g_cand[bi];
            g_nprob[m * SS + s] = p[bi];
            sc[bi] = -INFINITY;
        }
        __syncthreads();
    }
}

// GEMV slice: NC output cols at COL0, K reduce, 1024 threads, partials in s_scr.
#define GEMV_SLICE(W, LDN, COL0, X, NC, K)                                  \
  {                                                                         \
    const int G_ = (NC) / 4, P_ = 1024 / G_, KC_ = (K) / P_;                \
    const int g_ = tid % G_, p_ = tid / G_;                                 \
    const float4* W4_ = (const float4*)(W) + ((COL0) >> 2) + g_;            \
    const int ld4_ = (LDN) >> 2;                                            \
    float4 a_ = make_float4(0.f, 0.f, 0.f, 0.f);                            \
    int k_ = p_ * KC_;                                                      \
    _Pragma("unroll 8")                                                     \
    for (int kk_ = 0; kk_ < KC_; kk_++, k_++) {                             \
      float4 w4_ = W4_[(size_t)k_ * ld4_];                                  \
      float x_ = (X)[k_];                                                   \
      a_.x += x_ * w4_.x; a_.y += x_ * w4_.y;                               \
      a_.z += x_ * w4_.z; a_.w += x_ * w4_.w;                               \
    }                                                                       \
    ((float4*)s_scr)[p_ * G_ + g_] = a_;                                    \
  }                                                                         \
  __syncthreads();

__device__ __forceinline__ float4 redSlice(const float* s_scr, int g, int G, int P) {
    const float4* s4 = (const float4*)s_scr;
    float4 a = s4[g];
    for (int p = 1; p < P; p++) {
        float4 b = s4[p * G + g];
        a.x += b.x; a.y += b.y; a.z += b.z; a.w += b.w;
    }
    return a;
}

// ---------------- main kernel: 64 CTAs = 32 rows x 2 halves ----------------
__global__ void __launch_bounds__(1024) k_seq2(
    const int* __restrict__ marker, const float* __restrict__ timed,
    const float* __restrict__ maskd, const float* __restrict__ emb,
    const float* __restrict__ te_w, const float* __restrict__ te_b,
    const float* __restrict__ el_w, const float* __restrict__ el_b,
    const float* __restrict__ ml_w, const float* __restrict__ ml_b,
    const float* __restrict__ tl_w, const float* __restrict__ tl_b,
    const float* __restrict__ wq, const float* __restrict__ wk,
    const float* __restrict__ wv, const float* __restrict__ wo,
    const float* __restrict__ wo_b,
    const float* __restrict__ ln1s, const float* __restrict__ ln1b,
    const float* __restrict__ ff1w, const float* __restrict__ ff1b,
    const float* __restrict__ ff2w, const float* __restrict__ ff2b,
    const float* __restrict__ ln2s, const float* __restrict__ ln2b,
    float* __restrict__ out)
{
    const int tid = threadIdx.x;
    const int r = blockIdx.x >> 1;
    const int h = blockIdx.x & 1;
    const int col0 = h * 256;       // D-slice
    const int colF = h * 1024;      // DII-slice

    extern __shared__ float smb[];
    float* s_scr  = smb;                 // 4096
    float* h1s    = s_scr + 4096;        // 2048
    float* mds    = h1s + 2048;          // 512
    float* x1s    = mds + 512;           // 512
    float* ctxs   = x1s + 512;           // 512
    float* sints  = ctxs + 512;          // 512
    float* qs     = sints + 512;         // 256
    float* scs    = qs + 256;            // 256
    float* vv     = scs + 256;           // 128
    float* s_prob = vv + 128;            // LP
    float* s_nrec = s_prob + LP;         // LNN
    int*   s_cand = (int*)(s_nrec + LNN);// LP

    __shared__ float rs[32], rv[32]; __shared__ int ri[32];
    __shared__ float smw[SS]; __shared__ int snb[SS];
    __shared__ int sv_chosen;

    // ---- init (h==0 owns row state) ----
    if (h == 0) {
        for (int j = tid; j < LP;  j += 1024) { s_prob[j] = 0.f; s_cand[j] = 0; }
        for (int j = tid; j < LNN; j += 1024) s_nrec[j] = 0.f;
        if (tid == 0) {
            int m0 = marker[r * TT]; float t0 = timed[r * TT];
            s_prob[0] = 1.f; s_cand[0] = m0; s_nrec[0] = 1.f;
            sv_chosen = 0;
            g_lm[r] = m0; g_ltm[r] = t0;
            out[0 * (BB * TT) + r * TT] = (float)m0;
            out[1 * (BB * TT) + r * TT] = t0;
            out[2 * (BB * TT) + r * TT] = maskd[r * TT];
            out[3 * (BB * TT) + r * TT] = 1.f;
            out[4 * (BB * TT) + r * TT] = 1.f;
        }
    }
    rowBarrier(r);

    for (int i = 0; i < TMS; i++) {
        const int   lm = g_lm[r];
        const float lt = g_ltm[r];

        // ---- vvec + md slice (K=128) ----
        if (tid < EE) vv[tid] = emb[lm * EE + tid] + 0.1f * (lt * te_w[tid] + te_b[tid]);
        __syncthreads();
        GEMV_SLICE(el_w, DD, col0, vv, 256, 128)
        if (tid < 64) {
            float4 a = redSlice(s_scr, tid, 64, 16);
            float4 bq = ((const float4*)el_b)[(col0 >> 2) + tid];
            a.x += bq.x; a.y += bq.y; a.z += bq.z; a.w += bq.w;
            a.x = (a.x >= 0.f) ? a.x : 0.01f * a.x;
            a.y = (a.y >= 0.f) ? a.y : 0.01f * a.y;
            a.z = (a.z >= 0.f) ? a.z : 0.01f * a.z;
            a.w = (a.w >= 0.f) ? a.w : 0.01f * a.w;
            ((float4*)g_md)[((r * DD + col0) >> 2) + tid] = a;
        }
        rowBarrier(r);

        // ---- full md -> smem ----
        if (tid < 128) ((float4*)mds)[tid] = ((const float4*)g_md)[(r * DD >> 2) + tid];
        __syncthreads();

        // ---- q/k/v slices (heads 4h..4h+3) ----
        GEMV_SLICE(wq, DD, col0, mds, 256, 512)
        if (tid < 64) ((float4*)qs)[tid] = redSlice(s_scr, tid, 64, 16);
        __syncthreads();
        GEMV_SLICE(wk, DD, col0, mds, 256, 512)
        if (tid < 64)
            ((float4*)g_kc)[(((size_t)(r * TMS + i) * DD + col0) >> 2) + tid] =
                redSlice(s_scr, tid, 64, 16);
        __syncthreads();
        GEMV_SLICE(wv, DD, col0, mds, 256, 512)
        if (tid < 64)
            ((float4*)g_vc)[(((size_t)(r * TMS + i) * DD + col0) >> 2) + tid] =
                redSlice(s_scr, tid, 64, 16);
        __syncthreads();

        // ---- attention for 4 local heads ----
        if (tid < 4 * (i + 1)) {
            int t = tid >> 2, hh = tid & 3;
            const float4* kp = (const float4*)&g_kc[(size_t)(r * TMS + t) * DD + col0 + hh * 64];
            const float4* qp = (const float4*)&qs[hh * 64];
            float acc = 0.f;
#pragma unroll
            for (int d = 0; d < 16; d++) {
                float4 q4 = qp[d], k4 = kp[d];
                acc += q4.x * k4.x + q4.y * k4.y + q4.z * k4.z + q4.w * k4.w;
            }
            scs[hh * 64 + t] = acc * 0.125f;
        }
        __syncthreads();
        if (tid < 4) {
            int hh = tid;
            float mx = -INFINITY;
            for (int t = 0; t <= i; t++) mx = fmaxf(mx, scs[hh * 64 + t]);
            float sm = 0.f;
            for (int t = 0; t <= i; t++) { float e = expf(scs[hh * 64 + t] - mx); scs[hh * 64 + t] = e; sm += e; }
            for (int t = 0; t <= i; t++) scs[hh * 64 + t] /= sm;
        }
        __syncthreads();
        if (tid < 256) {
            int hh = tid >> 6;
            float acc = 0.f;
            for (int t = 0; t <= i; t++)
                acc += scs[hh * 64 + t] * g_vc[(size_t)(r * TMS + t) * DD + col0 + tid];
            g_ctx[r * DD + col0 + tid] = acc;
        }
        rowBarrier(r);

        // ---- full ctx -> smem; wo slice + LN1 partial stats ----
        if (tid < 128) ((float4*)ctxs)[tid] = ((const float4*)g_ctx)[(r * DD >> 2) + tid];
        __syncthreads();
        GEMV_SLICE(wo, DD, col0, ctxs, 256, 512)
        {
            float s1 = 0.f, s2 = 0.f;
            if (tid < 64) {
                float4 a = redSlice(s_scr, tid, 64, 16);
                float4 bq = ((const float4*)wo_b)[(col0 >> 2) + tid];
                float4 m4 = ((const float4*)mds)[(col0 >> 2) + tid];
                float4 val;
                val.x = m4.x + a.x + bq.x; val.y = m4.y + a.y + bq.y;
                val.z = m4.z + a.z + bq.z; val.w = m4.w + a.w + bq.w;
                ((float4*)g_x1r)[((r * DD + col0) >> 2) + tid] = val;
                s1 = val.x + val.y + val.z + val.w;
                s2 = val.x*val.x + val.y*val.y + val.z*val.z + val.w*val.w;
            }
            float S1 = blockSum(s1, rs);
            float S2 = blockSum(s2, rs);
            if (tid == 0) { g_st1[r * 8 + h * 2] = S1; g_st1[r * 8 + h * 2 + 1] = S2; }
        }
        rowBarrier(r);

        // ---- LN1 normalize full x1 -> smem; ff1 slice ----
        {
            float S1 = g_st1[r * 8] + g_st1[r * 8 + 2];
            float S2 = g_st1[r * 8 + 1] + g_st1[r * 8 + 3];
            float mn = S1 / (float)DD;
            float var = fmaxf(S2 / (float)DD - mn * mn, 0.f);
            float rsd = 1.f / sqrtf(var + 1e-5f);
            if (tid < 128) {
                float4 v4 = ((const float4*)g_x1r)[(r * DD >> 2) + tid];
                float4 g4 = ((const float4*)ln1s)[tid];
                float4 b4 = ((const float4*)ln1b)[tid];
                float4 o4;
                o4.x = (v4.x - mn) * rsd * g4.x + b4.x;
                o4.y = (v4.y - mn) * rsd * g4.y + b4.y;
                o4.z = (v4.z - mn) * rsd * g4.z + b4.z;
                o4.w = (v4.w - mn) * rsd * g4.w + b4.w;
                ((float4*)x1s)[tid] = o4;
            }
        }
        __syncthreads();
        GEMV_SLICE(ff1w, DII, colF, x1s, 1024, 512)
        if (tid < 256) {
            float4 a = redSlice(s_scr, tid, 256, 4);
            float4 b4 = ((const float4*)ff1b)[(colF >> 2) + tid];
            a.x = fmaxf(a.x + b4.x, 0.f); a.y = fmaxf(a.y + b4.y, 0.f);
            a.z = fmaxf(a.z + b4.z, 0.f); a.w = fmaxf(a.w + b4.w, 0.f);
            ((float4*)g_h1)[((r * DII + colF) >> 2) + tid] = a;
        }
        rowBarrier(r);

        // ---- full h1 -> smem; ff2 slice + LN2 partial stats ----
        if (tid < 512) ((float4*)h1s)[tid] = ((const float4*)g_h1)[(r * DII >> 2) + tid];
        __syncthreads();
        GEMV_SLICE(ff2w, DD, col0, h1s, 256, 2048)
        {
            float s1 = 0.f, s2 = 0.f;
            if (tid < 64) {
                float4 a = redSlice(s_scr, tid, 64, 16);
                float4 bq = ((const float4*)ff2b)[(col0 >> 2) + tid];
                float4 x4 = ((const float4*)x1s)[(col0 >> 2) + tid];
                float4 val;
                val.x = x4.x + a.x + bq.x; val.y = x4.y + a.y + bq.y;
                val.z = x4.z + a.z + bq.z; val.w = x4.w + a.w + bq.w;
                ((float4*)g_intr)[((r * DD + col0) >> 2) + tid] = val;
                s1 = val.x + val.y + val.z + val.w;
                s2 = val.x*val.x + val.y*val.y + val.z*val.z + val.w*val.w;
            }
            float S1 = blockSum(s1, rs);
            float S2 = blockSum(s2, rs);
            if (tid == 0) { g_st2[r * 8 + h * 2] = S1; g_st2[r * 8 + h * 2 + 1] = S2; }
        }
        rowBarrier(r);

        // ---- select (h==0 only) ----
        if (h == 0) {
            const int chosen = sv_chosen;
            {
                float S1 = g_st2[r * 8] + g_st2[r * 8 + 2];
                float S2 = g_st2[r * 8 + 1] + g_st2[r * 8 + 3];
                float mn = S1 / (float)DD;
                float var = fmaxf(S2 / (float)DD - mn * mn, 0.f);
                float rsd = 1.f / sqrtf(var + 1e-5f);
                if (tid < 128) {
                    float4 v4 = ((const float4*)g_intr)[(r * DD >> 2) + tid];
                    float4 g4 = ((const float4*)ln2s)[tid];
                    float4 b4 = ((const float4*)ln2b)[tid];
                    float4 o4;
                    o4.x = (v4.x - mn) * rsd * g4.x + b4.x;
                    o4.y = (v4.y - mn) * rsd * g4.y + b4.y;
                    o4.z = (v4.z - mn) * rsd * g4.z + b4.z;
                    o4.w = (v4.w - mn) * rsd * g4.w + b4.w;
                    ((float4*)sints)[tid] = o4;
                }
            }
            __syncthreads();

            float tv = 0.f, mv = 0.f;
            if (tid < DD) {
                tv = sints[tid] * tl_w[tid];
                mv = sints[tid] * ml_w[EE + tid];
            }
            float tdot = blockSum(tv, rs) + tl_b[0];
            float iml = blockSum(mv, rs);
            float nt = lt + (fmaxf(tdot, 0.f) + log1pf(expf(-fabsf(tdot))));

            if (tid < SS) {
                snb[tid] = g_nlist[lm * SS + tid];
                s_nrec[1 + i * SS + tid] = g_nprob[lm * SS + tid];
            }
            __syncthreads();
            if (tid < SS) {
                float acc = 0.f;
                const float4* ep = (const float4*)&emb[snb[tid] * EE];
                const float4* mw4 = (const float4*)ml_w;
#pragma unroll
                for (int e = 0; e < 32; e++) {
                    float4 a4 = ep[e], w4 = mw4[e];
                    acc += a4.x * w4.x + a4.y * w4.y + a4.z * w4.z + a4.w * w4.w;
                }
                smw[tid] = acc + iml + ml_b[0];
            }
            __syncthreads();
            if (tid < SS) {
                float v = smw[tid];
                float mx = v;
#pragma unroll
                for (int o = 16; o > 0; o >>= 1) mx = fmaxf(mx, __shfl_xor_sync(~0u, mx, o));
                float ex = expf(v - mx);
                float sm = ex;
#pragma unroll
                for (int o = 16; o > 0; o >>= 1) sm += __shfl_xor_sync(~0u, sm, o);
                float mp = ex / sm;
                float pc = s_prob[chosen];
                __syncwarp();
                float att = pc * mp;
                if (tid == 0) s_prob[chosen] = att;
                else {
                    s_prob[1 + i * (SS - 1) + tid - 1] = att;
                    s_cand[1 + i * (SS - 1) + tid - 1] = snb[tid];
                }
            }
            __syncthreads();

            uint32_t ka, kb;
            tf2x32(0u, 11u, 0u, (uint32_t)i, ka, kb);
            float bv = -INFINITY; int bi = 0x7fffffff;
            for (int j = tid; j < LP; j += 1024) {
                float z = logf(s_prob[j]) + gumbel_u32(rbits(ka, kb, (uint32_t)(r * LP + j)));
                if (z > bv) { bv = z; bi = j; }
            }
            blockArgmax(bv, bi, rv, ri);

            if (tid == 0) {
                int nc = bi, nm = s_cand[nc];
                sv_chosen = nc;
                g_lm[r] = nm; g_ltm[r] = nt;
                int o = r * TT + (i + 1);
                out[0 * (BB * TT) + o] = (float)nm;
                out[1 * (BB * TT) + o] = nt;
                out[2 * (BB * TT) + o] = (nt < 50.0f) ? 1.0f : 0.0f;
                out[3 * (BB * TT) + o] = s_nrec[nc];
                out[4 * (BB * TT) + o] = s_prob[nc];
            }
        }
        rowBarrier(r);
    }
}

extern "C" void kernel_launch(void* const* d_in, const int* in_sizes, int n_in,
                              void* d_out, int out_size) {
    const int*   marker = (const int*)  d_in[0];
    const float* timed  = (const float*)d_in[1];
    const float* maskd  = (const float*)d_in[2];
    const float* emb    = (const float*)d_in[3];
    const float* te_w   = (const float*)d_in[4];
    const float* te_b   = (const float*)d_in[5];
    const float* el_w   = (const float*)d_in[6];
    const float* el_b   = (const float*)d_in[7];
    const float* s1_w   = (const float*)d_in[8];
    const float* s1_b   = (const float*)d_in[9];
    const float* s2_w   = (const float*)d_in[10];
    const float* s2_b   = (const float*)d_in[11];
    const float* ml_w   = (const float*)d_in[12];
    const float* ml_b   = (const float*)d_in[13];
    const float* tl_w   = (const float*)d_in[14];
    const float* tl_b   = (const float*)d_in[15];
    const float* wq     = (const float*)d_in[16];
    const float* wk     = (const float*)d_in[17];
    const float* wv     = (const float*)d_in[18];
    const float* wo     = (const float*)d_in[19];
    const float* wo_b   = (const float*)d_in[20];
    const float* ln1_s  = (const float*)d_in[21];
    const float* ln1_b  = (const float*)d_in[22];
    const float* ff1_w  = (const float*)d_in[23];
    const float* ff1_b  = (const float*)d_in[24];
    const float* ff2_w  = (const float*)d_in[25];
    const float* ff2_b  = (const float*)d_in[26];
    const float* ln2_s  = (const float*)d_in[27];
    const float* ln2_b  = (const float*)d_in[28];
    float* out = (float*)d_out;

    static int inited = 0;
    if (!inited) {
        cudaFuncSetAttribute(k_seq2, cudaFuncAttributeMaxDynamicSharedMemorySize,
                             DYN_BYTES);
        inited = 1;
    }

    k_topk_cand<<<1, 1024>>>();
    k_bm<<<MM, EE>>>(emb, s1_w);
    k_a<<<CC, EE>>>(emb, s1_w);
    k_selectp<<<MM, CC>>>(s1_b, s2_w, s2_b);
    k_seq2<<<BB * 2, 1024, DYN_BYTES>>>(
        marker, timed, maskd, emb, te_w, te_b, el_w, el_b, ml_w, ml_b,
        tl_w, tl_b, wq, wk, wv, wo, wo_b, ln1_s, ln1_b,
        ff1_w, ff1_b, ff2_w, ff2_b, ln2_s, ln2_b, out);
}

// round 15
// speedup vs baseline: 2.0680x; 1.2423x over previous
#include <cuda_runtime.h>
#include <math.h>
#include <stdint.h>

#define MM 5000
#define EE 128
#define DD 512
#define DII 2048
#define CC 256
#define SS 32
#define BB 32
#define TT 64
#define TMS 63
#define LP 1954
#define LNN 2017
#define NG 16        // row groups (2 rows each)
#define SLC 4        // CTAs (slices) per group

#define DYN_FLOATS (8192 + 4096 + 1024 + 1024 + 1024 + 512 + 256 + 256 + 256 + LP + LNN + LP)
#define DYN_BYTES (DYN_FLOATS * 4)

// ---------------- device state ----------------
__device__ int   g_cand[CC];
__device__ float g_At[EE * CC];
__device__ float g_Bm[MM * EE];
__device__ int   g_nlist[MM * SS];
__device__ float g_nprob[MM * SS];

__device__ float g_kc[BB * TMS * DD];
__device__ float g_vc[BB * TMS * DD];
__device__ float g_ctx[BB * DD];
__device__ float g_x1r[BB * DD];
__device__ float g_h1[BB * DII];
__device__ float g_intr[BB * DD];
__device__ float g_st1[BB * 16];
__device__ float g_st2[BB * 16];
__device__ int   g_lm[BB];
__device__ float g_ltm[BB];

__device__ int          g_rcnt[NG * 32];
__device__ volatile int g_rgen[NG * 32];

__device__ __forceinline__ void rowBarrier(int grp) {
    __syncthreads();
    if (threadIdx.x == 0) {
        volatile int* genp = &g_rgen[grp * 32];
        int gen = *genp;
        __threadfence();
        if (atomicAdd(&g_rcnt[grp * 32], 1) == SLC - 1) {
            g_rcnt[grp * 32] = 0;
            __threadfence();
            *genp = gen + 1;
        } else {
            while (*genp == gen) __nanosleep(32);
        }
        __threadfence();
    }
    __syncthreads();
}

__device__ __forceinline__ void add4(float4& a, const float4& b) {
    a.x += b.x; a.y += b.y; a.z += b.z; a.w += b.w;
}

// ---------------- threefry (JAX partitionable) ----------------
__device__ __forceinline__ void tf2x32(uint32_t k0, uint32_t k1, uint32_t x0, uint32_t x1,
                                       uint32_t& o0, uint32_t& o1) {
    uint32_t k2 = k0 ^ k1 ^ 0x1BD11BDAu;
    x0 += k0; x1 += k1;
#define TF_R(r) { x0 += x1; x1 = (x1 << r) | (x1 >> (32 - r)); x1 ^= x0; }
    TF_R(13) TF_R(15) TF_R(26) TF_R(6)   x0 += k1; x1 += k2 + 1u;
    TF_R(17) TF_R(29) TF_R(16) TF_R(24)  x0 += k2; x1 += k0 + 2u;
    TF_R(13) TF_R(15) TF_R(26) TF_R(6)   x0 += k0; x1 += k1 + 3u;
    TF_R(17) TF_R(29) TF_R(16) TF_R(24)  x0 += k1; x1 += k2 + 4u;
    TF_R(13) TF_R(15) TF_R(26) TF_R(6)   x0 += k2; x1 += k0 + 5u;
#undef TF_R
    o0 = x0; o1 = x1;
}
__device__ __forceinline__ uint32_t rbits(uint32_t k0, uint32_t k1, uint32_t idx) {
    uint32_t a, b; tf2x32(k0, k1, 0u, idx, a, b); return a ^ b;
}
__device__ __forceinline__ float gumbel_u32(uint32_t bits) {
    const float tiny = 1.17549435e-38f;
    float f = __uint_as_float((bits >> 9) | 0x3f800000u) - 1.0f;
    float u = fmaxf(tiny, f + tiny);
    return -logf(-logf(u));
}

// ---------------- reductions ----------------
__device__ __forceinline__ float blockSum(float v, float* rs) {
    int tid = threadIdx.x, w = tid >> 5, l = tid & 31, nw = blockDim.x >> 5;
#pragma unroll
    for (int o = 16; o > 0; o >>= 1) v += __shfl_xor_sync(~0u, v, o);
    if (l == 0) rs[w] = v;
    __syncthreads();
    if (w == 0) {
        float x = (l < nw) ? rs[l] : 0.0f;
#pragma unroll
        for (int o = 16; o > 0; o >>= 1) x += __shfl_xor_sync(~0u, x, o);
        if (l == 0) rs[0] = x;
    }
    __syncthreads();
    float r = rs[0]; __syncthreads(); return r;
}
__device__ __forceinline__ float blockMax(float v, float* rs) {
    int tid = threadIdx.x, w = tid >> 5, l = tid & 31, nw = blockDim.x >> 5;
#pragma unroll
    for (int o = 16; o > 0; o >>= 1) v = fmaxf(v, __shfl_xor_sync(~0u, v, o));
    if (l == 0) rs[w] = v;
    __syncthreads();
    if (w == 0) {
        float x = (l < nw) ? rs[l] : -INFINITY;
#pragma unroll
        for (int o = 16; o > 0; o >>= 1) x = fmaxf(x, __shfl_xor_sync(~0u, x, o));
        if (l == 0) rs[0] = x;
    }
    __syncthreads();
    float r = rs[0]; __syncthreads(); return r;
}
__device__ __forceinline__ void warpArgmax(float& v, int& idx) {
#pragma unroll
    for (int o = 16; o > 0; o >>= 1) {
        float ov = __shfl_xor_sync(~0u, v, o);
        int   oi = __shfl_xor_sync(~0u, idx, o);
        if (ov > v || (ov == v && oi < idx)) { v = ov; idx = oi; }
    }
}
__device__ __forceinline__ void blockArgmax(float& v, int& idx, float* rv, int* ri) {
    int tid = threadIdx.x, w = tid >> 5, l = tid & 31, nw = (blockDim.x + 31) >> 5;
    warpArgmax(v, idx);
    if (l == 0) { rv[w] = v; ri[w] = idx; }
    __syncthreads();
    if (w == 0) {
        float vv = (l < nw) ? rv[l] : -INFINITY;
        int   ii = (l < nw) ? ri[l] : 0x7fffffff;
        warpArgmax(vv, ii);
        if (l == 0) { rv[0] = vv; ri[0] = ii; }
    }
    __syncthreads();
    v = rv[0]; idx = ri[0]; __syncthreads();
}

// ---------------- precompute (proven) ----------------
__global__ void __launch_bounds__(1024) k_topk_cand() {
    __shared__ float vals[MM];
    __shared__ float rv[32]; __shared__ int ri[32];
    uint32_t ka, kb; tf2x32(0u, 7u, 0u, 0u, ka, kb);
    for (int i = threadIdx.x; i < MM; i += blockDim.x)
        vals[i] = gumbel_u32(rbits(ka, kb, (uint32_t)i));
    __syncthreads();
    for (int r = 0; r < CC; r++) {
        float bv = -INFINITY; int bi = 0x7fffffff;
        for (int i = threadIdx.x; i < MM; i += blockDim.x) {
            float v = vals[i];
            if (v > bv) { bv = v; bi = i; }
        }
        blockArgmax(bv, bi, rv, ri);
        if (threadIdx.x == 0) { g_cand[r] = bi; vals[bi] = -INFINITY; }
        __syncthreads();
    }
}

__global__ void __launch_bounds__(EE) k_bm(const float* __restrict__ emb,
                                           const float* __restrict__ s1w) {
    __shared__ float se[EE];
    int m = blockIdx.x, d = threadIdx.x;
    se[d] = emb[m * EE + d];
    __syncthreads();
    float acc = 0.0f;
#pragma unroll 8
    for (int e = 0; e < EE; e++) acc += se[e] * s1w[(EE + e) * EE + d];
    g_Bm[m * EE + d] = acc;
}

__global__ void __launch_bounds__(EE) k_a(const float* __restrict__ emb,
                                          const float* __restrict__ s1w) {
    __shared__ float se[EE];
    int c = blockIdx.x, d = threadIdx.x;
    se[d] = emb[g_cand[c] * EE + d];
    __syncthreads();
    float acc = 0.0f;
#pragma unroll 8
    for (int e = 0; e < EE; e++) acc += se[e] * s1w[e * EE + d];
    g_At[d * CC + c] = acc;
}

__global__ void __launch_bounds__(CC) k_selectp(const float* __restrict__ s1b,
                                                const float* __restrict__ s2w,
                                                const float* __restrict__ s2b) {
    __shared__ float sb[EE], sw[EE], sbm[EE];
    __shared__ float p[CC], sc[CC];
    __shared__ float rs[32], rv[32]; __shared__ int ri[32];
    int m = blockIdx.x, c = threadIdx.x;
    if (c < EE) { sb[c] = s1b[c]; sw[c] = s2w[c]; sbm[c] = g_Bm[m * EE + c]; }
    __syncthreads();
    float acc = 0.0f;
#pragma unroll 4
    for (int e = 0; e < EE; e++) {
        float t = g_At[e * CC + c] + sbm[e] + sb[e];
        t = (t >= 0.0f) ? t : 0.01f * t;
        acc += t * sw[e];
    }
    float logit = acc + s2b[0];
    float mx = blockMax(logit, rs);
    float ex = expf(logit - mx);
    float sm = blockSum(ex, rs);
    float pc = ex / sm;
    p[c] = pc;
    uint32_t ka, kb; tf2x32(0u, 7u, 0u, 1u, ka, kb);
    sc[c] = logf(pc) + gumbel_u32(rbits(ka, kb, (uint32_t)(m * CC + c)));
    __syncthreads();
    for (int s = 0; s < SS; s++) {
        float bv = sc[c]; int bi = c;
        blockArgmax(bv, bi, rv, ri);
        if (threadIdx.x == 0) {
            g_nlist[m * SS + s] = g_cand[bi];
            g_nprob[m * SS + s] = p[bi];
            sc[bi] = -INFINITY;
        }
        __syncthreads();
    }
}

// 2-row GEMV slice: NC cols at COL0, K reduce, 1024 threads.
#define GEMV2(W, LDN, COL0, X0, X1, NC, K)                                  \
  {                                                                         \
    const int G_ = (NC) / 4, P_ = 1024 / G_, KC_ = (K) / P_;                \
    const int g_ = tid % G_, p_ = tid / G_;                                 \
    const float4* W4_ = (const float4*)(W) + ((COL0) >> 2) + g_;            \
    const int ld4_ = (LDN) >> 2;                                            \
    float4 a0_ = make_float4(0.f,0.f,0.f,0.f), a1_ = a0_;                   \
    int k_ = p_ * KC_;                                                      \
    _Pragma("unroll 8")                                                     \
    for (int kk_ = 0; kk_ < KC_; kk_++, k_++) {                             \
      float4 w4_ = W4_[(size_t)k_ * ld4_];                                  \
      float xa_ = (X0)[k_], xb_ = (X1)[k_];                                 \
      a0_.x += xa_*w4_.x; a0_.y += xa_*w4_.y; a0_.z += xa_*w4_.z; a0_.w += xa_*w4_.w; \
      a1_.x += xb_*w4_.x; a1_.y += xb_*w4_.y; a1_.z += xb_*w4_.z; a1_.w += xb_*w4_.w; \
    }                                                                       \
    scr4[p_ * G_ + g_] = a0_;                                               \
    scr4[1024 + p_ * G_ + g_] = a1_;                                        \
  }                                                                         \
  __syncthreads();

__device__ __forceinline__ float4 redSlice2(const float4* scr4, int r2, int g, int G, int P) {
    float4 a = scr4[r2 * 1024 + g];
    for (int p = 1; p < P; p++) add4(a, scr4[r2 * 1024 + p * G + g]);
    return a;
}

// ---------------- main: 64 CTAs = 16 groups x 4 slices, 2 rows/group ----------------
__global__ void __launch_bounds__(1024) k_seq3(
    const int* __restrict__ marker, const float* __restrict__ timed,
    const float* __restrict__ maskd, const float* __restrict__ emb,
    const float* __restrict__ te_w, const float* __restrict__ te_b,
    const float* __restrict__ el_w, const float* __restrict__ el_b,
    const float* __restrict__ ml_w, const float* __restrict__ ml_b,
    const float* __restrict__ tl_w, const float* __restrict__ tl_b,
    const float* __restrict__ wq, const float* __restrict__ wk,
    const float* __restrict__ wv, const float* __restrict__ wo,
    const float* __restrict__ wo_b,
    const float* __restrict__ ln1s, const float* __restrict__ ln1b,
    const float* __restrict__ ff1w, const float* __restrict__ ff1b,
    const float* __restrict__ ff2w, const float* __restrict__ ff2b,
    const float* __restrict__ ln2s, const float* __restrict__ ln2b,
    float* __restrict__ out)
{
    const int tid = threadIdx.x;
    const int grp = blockIdx.x >> 2;
    const int slc = blockIdx.x & 3;
    const int col0 = slc * 128;      // D slice (= heads 2slc, 2slc+1)
    const int colF = slc * 512;      // DII slice
    const int r0 = grp * 2;

    extern __shared__ float smb[];
    float4* scr4  = (float4*)smb;            // 2048 f4 = 8192 floats
    float* h1s    = smb + 8192;              // 4096
    float* mds    = h1s + 4096;              // 1024
    float* x1s    = mds + 1024;              // 1024
    float* ctxs   = x1s + 1024;              // 1024
    float* sints  = ctxs + 1024;             // 512
    float* qs     = sints + 512;             // 256
    float* scs    = qs + 256;                // 256
    float* vv     = scs + 256;               // 256
    float* s_prob = vv + 256;                // LP
    float* s_nrec = s_prob + LP;             // LNN
    int*   s_cand = (int*)(s_nrec + LNN);    // LP

    __shared__ float rs[32], rv[32]; __shared__ int ri[32];
    __shared__ float smw[SS]; __shared__ int snb[SS];
    __shared__ float sstat[4];
    __shared__ int sv_chosen;

    // ---- init (slices 0/1 own rows r0+0 / r0+1) ----
    if (slc < 2) {
        int r = r0 + slc;
        for (int j = tid; j < LP;  j += 1024) { s_prob[j] = 0.f; s_cand[j] = 0; }
        for (int j = tid; j < LNN; j += 1024) s_nrec[j] = 0.f;
        if (tid == 0) {
            int m0 = marker[r * TT]; float t0 = timed[r * TT];
            s_prob[0] = 1.f; s_cand[0] = m0; s_nrec[0] = 1.f;
            sv_chosen = 0;
            g_lm[r] = m0; g_ltm[r] = t0;
            out[0 * (BB * TT) + r * TT] = (float)m0;
            out[1 * (BB * TT) + r * TT] = t0;
            out[2 * (BB * TT) + r * TT] = maskd[r * TT];
            out[3 * (BB * TT) + r * TT] = 1.f;
            out[4 * (BB * TT) + r * TT] = 1.f;
        }
    }
    rowBarrier(grp);

    for (int i = 0; i < TMS; i++) {
        const int   lm0 = g_lm[r0],     lm1 = g_lm[r0 + 1];
        const float lt0 = g_ltm[r0],    lt1 = g_ltm[r0 + 1];

        // ---- vvec (2 rows) + FULL md locally ----
        if (tid < 256) {
            int r2 = tid >> 7, e = tid & 127;
            int lmr = r2 ? lm1 : lm0; float ltr = r2 ? lt1 : lt0;
            vv[tid] = emb[lmr * EE + e] + 0.1f * (ltr * te_w[e] + te_b[e]);
        }
        __syncthreads();
        GEMV2(el_w, DD, 0, vv, vv + 128, 512, 128)
        if (tid < 256) {
            int r2 = tid >> 7, g2 = tid & 127;
            float4 a = redSlice2(scr4, r2, g2, 128, 8);
            float4 bq = ((const float4*)el_b)[g2];
            a.x += bq.x; a.y += bq.y; a.z += bq.z; a.w += bq.w;
            a.x = (a.x >= 0.f) ? a.x : 0.01f * a.x;
            a.y = (a.y >= 0.f) ? a.y : 0.01f * a.y;
            a.z = (a.z >= 0.f) ? a.z : 0.01f * a.z;
            a.w = (a.w >= 0.f) ? a.w : 0.01f * a.w;
            ((float4*)mds)[r2 * 128 + g2] = a;
        }
        __syncthreads();

        // ---- q / k / v slices (heads 2slc..2slc+1, 2 rows) ----
        GEMV2(wq, DD, col0, mds, mds + 512, 128, 512)
        if (tid < 64) {
            int r2 = tid >> 5, g2 = tid & 31;
            ((float4*)qs)[r2 * 32 + g2] = redSlice2(scr4, r2, g2, 32, 32);
        }
        __syncthreads();
        GEMV2(wk, DD, col0, mds, mds + 512, 128, 512)
        if (tid < 64) {
            int r2 = tid >> 5, g2 = tid & 31;
            int r = r0 + r2;
            ((float4*)g_kc)[(((size_t)(r * TMS + i) * DD + col0) >> 2) + g2] =
                redSlice2(scr4, r2, g2, 32, 32);
        }
        __syncthreads();
        GEMV2(wv, DD, col0, mds, mds + 512, 128, 512)
        if (tid < 64) {
            int r2 = tid >> 5, g2 = tid & 31;
            int r = r0 + r2;
            ((float4*)g_vc)[(((size_t)(r * TMS + i) * DD + col0) >> 2) + g2] =
                redSlice2(scr4, r2, g2, 32, 32);
        }
        __syncthreads();

        // ---- attention (2 heads x 2 rows) ----
        if (tid < 4 * (i + 1)) {
            int u = tid & 3, t = tid >> 2;
            int r2 = u >> 1, hh = u & 1;
            int r = r0 + r2;
            const float4* kp = (const float4*)&g_kc[(size_t)(r * TMS + t) * DD + col0 + hh * 64];
            const float4* qp = (const float4*)&qs[r2 * 128 + hh * 64];
            float acc = 0.f;
#pragma unroll
            for (int d = 0; d < 16; d++) {
                float4 q4 = qp[d], k4 = kp[d];
                acc += q4.x * k4.x + q4.y * k4.y + q4.z * k4.z + q4.w * k4.w;
            }
            scs[r2 * 128 + hh * 64 + t] = acc * 0.125f;
        }
        __syncthreads();
        if (tid < 4) {
            int r2 = tid >> 1, hh = tid & 1;
            float* sp = &scs[r2 * 128 + hh * 64];
            float mx = -INFINITY;
            for (int t = 0; t <= i; t++) mx = fmaxf(mx, sp[t]);
            float sm = 0.f;
            for (int t = 0; t <= i; t++) { float e = expf(sp[t] - mx); sp[t] = e; sm += e; }
            for (int t = 0; t <= i; t++) sp[t] /= sm;
        }
        __syncthreads();
        if (tid < 256) {
            int r2 = tid >> 7, d = tid & 127;
            int hh = d >> 6;
            int r = r0 + r2;
            float acc = 0.f;
            for (int t = 0; t <= i; t++)
                acc += scs[r2 * 128 + hh * 64 + (t)] * g_vc[(size_t)(r * TMS + t) * DD + col0 + d];
            g_ctx[r * DD + col0 + d] = acc;
        }
        rowBarrier(grp);   // A

        // ---- full ctx; wo slice + LN1 partial stats ----
        if (tid < 256) ((float4*)ctxs)[tid] = ((const float4*)g_ctx)[((size_t)r0 * DD >> 2) + tid];
        __syncthreads();
        GEMV2(wo, DD, col0, ctxs, ctxs + 512, 128, 512)
        if (tid < 64) {
            int r2 = tid >> 5, g2 = tid & 31;
            int r = r0 + r2;
            float4 a = redSlice2(scr4, r2, g2, 32, 32);
            float4 bq = ((const float4*)wo_b)[(col0 >> 2) + g2];
            float4 m4 = ((const float4*)mds)[r2 * 128 + (col0 >> 2) + g2];
            float4 val;
            val.x = m4.x + a.x + bq.x; val.y = m4.y + a.y + bq.y;
            val.z = m4.z + a.z + bq.z; val.w = m4.w + a.w + bq.w;
            ((float4*)g_x1r)[(((size_t)r * DD + col0) >> 2) + g2] = val;
            float s1 = val.x + val.y + val.z + val.w;
            float s2 = val.x*val.x + val.y*val.y + val.z*val.z + val.w*val.w;
#pragma unroll
            for (int o = 16; o >= 1; o >>= 1) {
                s1 += __shfl_xor_sync(~0u, s1, o);
                s2 += __shfl_xor_sync(~0u, s2, o);
            }
            if (g2 == 0) {
                g_st1[r * 16 + slc * 2] = s1;
                g_st1[r * 16 + slc * 2 + 1] = s2;
            }
        }
        rowBarrier(grp);   // B

        // ---- LN1 -> x1s; ff1 slice ----
        if (tid < 2) {
            int r = r0 + tid;
            float S1 = 0.f, S2 = 0.f;
#pragma unroll
            for (int s2i = 0; s2i < SLC; s2i++) {
                S1 += g_st1[r * 16 + s2i * 2];
                S2 += g_st1[r * 16 + s2i * 2 + 1];
            }
            float mn = S1 / (float)DD;
            float var = fmaxf(S2 / (float)DD - mn * mn, 0.f);
            sstat[tid * 2] = mn;
            sstat[tid * 2 + 1] = 1.f / sqrtf(var + 1e-5f);
        }
        __syncthreads();
        if (tid < 256) {
            int r2 = tid >> 7, c4 = tid & 127;
            float mn = sstat[r2 * 2], rsd = sstat[r2 * 2 + 1];
            float4 v4 = ((const float4*)g_x1r)[((size_t)r0 * DD >> 2) + tid];
            float4 g4 = ((const float4*)ln1s)[c4];
            float4 b4 = ((const float4*)ln1b)[c4];
            float4 o4;
            o4.x = (v4.x - mn) * rsd * g4.x + b4.x;
            o4.y = (v4.y - mn) * rsd * g4.y + b4.y;
            o4.z = (v4.z - mn) * rsd * g4.z + b4.z;
            o4.w = (v4.w - mn) * rsd * g4.w + b4.w;
            ((float4*)x1s)[tid] = o4;
        }
        __syncthreads();
        GEMV2(ff1w, DII, colF, x1s, x1s + 512, 512, 512)
        if (tid < 256) {
            int r2 = tid >> 7, g2 = tid & 127;
            int r = r0 + r2;
            float4 a = redSlice2(scr4, r2, g2, 128, 8);
            float4 b4 = ((const float4*)ff1b)[(colF >> 2) + g2];
            a.x = fmaxf(a.x + b4.x, 0.f); a.y = fmaxf(a.y + b4.y, 0.f);
            a.z = fmaxf(a.z + b4.z, 0.f); a.w = fmaxf(a.w + b4.w, 0.f);
            ((float4*)g_h1)[(((size_t)r * DII + colF) >> 2) + g2] = a;
        }
        rowBarrier(grp);   // C

        // ---- full h1; ff2 slice + LN2 partial stats ----
        ((float4*)h1s)[tid] = ((const float4*)g_h1)[((size_t)r0 * DII >> 2) + tid];
        __syncthreads();
        GEMV2(ff2w, DD, col0, h1s, h1s + 2048, 128, 2048)
        if (tid < 64) {
            int r2 = tid >> 5, g2 = tid & 31;
            int r = r0 + r2;
            float4 a = redSlice2(scr4, r2, g2, 32, 32);
            float4 bq = ((const float4*)ff2b)[(col0 >> 2) + g2];
            float4 x4 = ((const float4*)x1s)[r2 * 128 + (col0 >> 2) + g2];
            float4 val;
            val.x = x4.x + a.x + bq.x; val.y = x4.y + a.y + bq.y;
            val.z = x4.z + a.z + bq.z; val.w = x4.w + a.w + bq.w;
            ((float4*)g_intr)[(((size_t)r * DD + col0) >> 2) + g2] = val;
            float s1 = val.x + val.y + val.z + val.w;
            float s2 = val.x*val.x + val.y*val.y + val.z*val.z + val.w*val.w;
#pragma unroll
            for (int o = 16; o >= 1; o >>= 1) {
                s1 += __shfl_xor_sync(~0u, s1, o);
                s2 += __shfl_xor_sync(~0u, s2, o);
            }
            if (g2 == 0) {
                g_st2[r * 16 + slc * 2] = s1;
                g_st2[r * 16 + slc * 2 + 1] = s2;
            }
        }
        rowBarrier(grp);   // D

        // ---- select (slices 0/1; row r0+slc) ----
        if (slc < 2) {
            const int r = r0 + slc;
            const int lm = slc ? lm1 : lm0;
            const float lt = slc ? lt1 : lt0;
            const int chosen = sv_chosen;

            if (tid == 0) {
                float S1 = 0.f, S2 = 0.f;
#pragma unroll
                for (int s2i = 0; s2i < SLC; s2i++) {
                    S1 += g_st2[r * 16 + s2i * 2];
                    S2 += g_st2[r * 16 + s2i * 2 + 1];
                }
                float mn = S1 / (float)DD;
                float var = fmaxf(S2 / (float)DD - mn * mn, 0.f);
                sstat[0] = mn;
                sstat[1] = 1.f / sqrtf(var + 1e-5f);
            }
            __syncthreads();
            if (tid < 128) {
                float mn = sstat[0], rsd = sstat[1];
                float4 v4 = ((const float4*)g_intr)[((size_t)r * DD >> 2) + tid];
                float4 g4 = ((const float4*)ln2s)[tid];
                float4 b4 = ((const float4*)ln2b)[tid];
                float4 o4;
                o4.x = (v4.x - mn) * rsd * g4.x + b4.x;
                o4.y = (v4.y - mn) * rsd * g4.y + b4.y;
                o4.z = (v4.z - mn) * rsd * g4.z + b4.z;
                o4.w = (v4.w - mn) * rsd * g4.w + b4.w;
                ((float4*)sints)[tid] = o4;
            }
            __syncthreads();

            float tv = 0.f, mv = 0.f;
            if (tid < DD) {
                tv = sints[tid] * tl_w[tid];
                mv = sints[tid] * ml_w[EE + tid];
            }
            float tdot = blockSum(tv, rs) + tl_b[0];
            float iml = blockSum(mv, rs);
            float nt = lt + (fmaxf(tdot, 0.f) + log1pf(expf(-fabsf(tdot))));

            if (tid < SS) {
                snb[tid] = g_nlist[lm * SS + tid];
                s_nrec[1 + i * SS + tid] = g_nprob[lm * SS + tid];
            }
            __syncthreads();
            if (tid < SS) {
                float acc = 0.f;
                const float4* ep = (const float4*)&emb[snb[tid] * EE];
                const float4* mw4 = (const float4*)ml_w;
#pragma unroll
                for (int e = 0; e < 32; e++) {
                    float4 a4 = ep[e], w4 = mw4[e];
                    acc += a4.x * w4.x + a4.y * w4.y + a4.z * w4.z + a4.w * w4.w;
                }
                smw[tid] = acc + iml + ml_b[0];
            }
            __syncthreads();
            if (tid < SS) {
                float v = smw[tid];
                float mx = v;
#pragma unroll
                for (int o = 16; o > 0; o >>= 1) mx = fmaxf(mx, __shfl_xor_sync(~0u, mx, o));
                float ex = expf(v - mx);
                float sm = ex;
#pragma unroll
                for (int o = 16; o > 0; o >>= 1) sm += __shfl_xor_sync(~0u, sm, o);
                float mp = ex / sm;
                float pc = s_prob[chosen];
                __syncwarp();
                float att = pc * mp;
                if (tid == 0) s_prob[chosen] = att;
                else {
                    s_prob[1 + i * (SS - 1) + tid - 1] = att;
                    s_cand[1 + i * (SS - 1) + tid - 1] = snb[tid];
                }
            }
            __syncthreads();

            uint32_t ka, kb;
            tf2x32(0u, 11u, 0u, (uint32_t)i, ka, kb);
            float bv = -INFINITY; int bi = 0x7fffffff;
            for (int j = tid; j < LP; j += 1024) {
                float z = logf(s_prob[j]) + gumbel_u32(rbits(ka, kb, (uint32_t)(r * LP + j)));
                if (z > bv) { bv = z; bi = j; }
            }
            blockArgmax(bv, bi, rv, ri);

            if (tid == 0) {
                int nc = bi, nm = s_cand[nc];
                sv_chosen = nc;
                g_lm[r] = nm; g_ltm[r] = nt;
                int o = r * TT + (i + 1);
                out[0 * (BB * TT) + o] = (float)nm;
                out[1 * (BB * TT) + o] = nt;
                out[2 * (BB * TT) + o] = (nt < 50.0f) ? 1.0f : 0.0f;
                out[3 * (BB * TT) + o] = s_nrec[nc];
                out[4 * (BB * TT) + o] = s_prob[nc];
            }
        }
        rowBarrier(grp);   // E
    }
}

extern "C" void kernel_launch(void* const* d_in, const int* in_sizes, int n_in,
                              void* d_out, int out_size) {
    const int*   marker = (const int*)  d_in[0];
    const float* timed  = (const float*)d_in[1];
    const float* maskd  = (const float*)d_in[2];
    const float* emb    = (const float*)d_in[3];
    const float* te_w   = (const float*)d_in[4];
    const float* te_b   = (const float*)d_in[5];
    const float* el_w   = (const float*)d_in[6];
    const float* el_b   = (const float*)d_in[7];
    const float* s1_w   = (const float*)d_in[8];
    const float* s1_b   = (const float*)d_in[9];
    const float* s2_w   = (const float*)d_in[10];
    const float* s2_b   = (const float*)d_in[11];
    const float* ml_w   = (const float*)d_in[12];
    const float* ml_b   = (const float*)d_in[13];
    const float* tl_w   = (const float*)d_in[14];
    const float* tl_b   = (const float*)d_in[15];
    const float* wq     = (const float*)d_in[16];
    const float* wk     = (const float*)d_in[17];
    const float* wv     = (const float*)d_in[18];
    const float* wo     = (const float*)d_in[19];
    const float* wo_b   = (const float*)d_in[20];
    const float* ln1_s  = (const float*)d_in[21];
    const float* ln1_b  = (const float*)d_in[22];
    const float* ff1_w  = (const float*)d_in[23];
    const float* ff1_b  = (const float*)d_in[24];
    const float* ff2_w  = (const float*)d_in[25];
    const float* ff2_b  = (const float*)d_in[26];
    const float* ln2_s  = (const float*)d_in[27];
    const float* ln2_b  = (const float*)d_in[28];
    float* out = (float*)d_out;

    static int inited = 0;
    if (!inited) {
        cudaFuncSetAttribute(k_seq3, cudaFuncAttributeMaxDynamicSharedMemorySize,
                             DYN_BYTES);
        inited = 1;
    }

    k_topk_cand<<<1, 1024>>>();
    k_bm<<<MM, EE>>>(emb, s1_w);
    k_a<<<CC, EE>>>(emb, s1_w);
    k_selectp<<<MM, CC>>>(s1_b, s2_w, s2_b);
    k_seq3<<<NG * SLC, 1024, DYN_BYTES>>>(
        marker, timed, maskd, emb, te_w, te_b, el_w, el_b, ml_w, ml_b,
        tl_w, tl_b, wq, wk, wv, wo, wo_b, ln1_s, ln1_b,
        ff1_w, ff1_b, ff2_w, ff2_b, ln2_s, ln2_b, out);
}

// round 16
// speedup vs baseline: 2.1902x; 1.0591x over previous
#include <cuda_runtime.h>
#include <math.h>
#include <stdint.h>

#define MM 5000
#define EE 128
#define DD 512
#define DII 2048
#define CC 256
#define SS 32
#define BB 32
#define TT 64
#define TMS 63
#define LP 1954
#define LNN 2017
#define NG 8         // row groups (4 rows each)
#define SLC 8        // CTAs (slices) per group
#define RPC 4        // rows per group

#define DYN_FLOATS (16384 + 8192 + 2048 + 2048 + 2048 + 512 + 256 + 256 + 512 + LP + LNN + LP)
#define DYN_BYTES (DYN_FLOATS * 4)

// ---------------- device state ----------------
__device__ int   g_cand[CC];
__device__ float g_At[EE * CC];
__device__ float g_Bm[MM * EE];
__device__ int   g_nlist[MM * SS];
__device__ float g_nprob[MM * SS];

__device__ float g_kc[BB * TMS * DD];
__device__ float g_vc[BB * TMS * DD];
__device__ float g_ctx[BB * DD];
__device__ float g_x1r[BB * DD];
__device__ float g_h1[BB * DII];
__device__ float g_intr[BB * DD];
__device__ float g_st1[BB * 16];
__device__ float g_st2[BB * 16];
__device__ int   g_lm[BB];
__device__ float g_ltm[BB];

__device__ int          g_rcnt[NG * 32];
__device__ volatile int g_rgen[NG * 32];

__device__ __forceinline__ void rowBarrier(int grp) {
    __syncthreads();
    if (threadIdx.x == 0) {
        volatile int* genp = &g_rgen[grp * 32];
        int gen = *genp;
        __threadfence();
        if (atomicAdd(&g_rcnt[grp * 32], 1) == SLC - 1) {
            g_rcnt[grp * 32] = 0;
            __threadfence();
            *genp = gen + 1;
        } else {
            while (*genp == gen) __nanosleep(32);
        }
        __threadfence();
    }
    __syncthreads();
}

__device__ __forceinline__ void add4(float4& a, const float4& b) {
    a.x += b.x; a.y += b.y; a.z += b.z; a.w += b.w;
}
__device__ __forceinline__ void fm4(float4& a, float s, const float4& b) {
    a.x += s * b.x; a.y += s * b.y; a.z += s * b.z; a.w += s * b.w;
}

// ---------------- threefry (JAX partitionable) ----------------
__device__ __forceinline__ void tf2x32(uint32_t k0, uint32_t k1, uint32_t x0, uint32_t x1,
                                       uint32_t& o0, uint32_t& o1) {
    uint32_t k2 = k0 ^ k1 ^ 0x1BD11BDAu;
    x0 += k0; x1 += k1;
#define TF_R(r) { x0 += x1; x1 = (x1 << r) | (x1 >> (32 - r)); x1 ^= x0; }
    TF_R(13) TF_R(15) TF_R(26) TF_R(6)   x0 += k1; x1 += k2 + 1u;
    TF_R(17) TF_R(29) TF_R(16) TF_R(24)  x0 += k2; x1 += k0 + 2u;
    TF_R(13) TF_R(15) TF_R(26) TF_R(6)   x0 += k0; x1 += k1 + 3u;
    TF_R(17) TF_R(29) TF_R(16) TF_R(24)  x0 += k1; x1 += k2 + 4u;
    TF_R(13) TF_R(15) TF_R(26) TF_R(6)   x0 += k2; x1 += k0 + 5u;
#undef TF_R
    o0 = x0; o1 = x1;
}
__device__ __forceinline__ uint32_t rbits(uint32_t k0, uint32_t k1, uint32_t idx) {
    uint32_t a, b; tf2x32(k0, k1, 0u, idx, a, b); return a ^ b;
}
__device__ __forceinline__ float gumbel_u32(uint32_t bits) {
    const float tiny = 1.17549435e-38f;
    float f = __uint_as_float((bits >> 9) | 0x3f800000u) - 1.0f;
    float u = fmaxf(tiny, f + tiny);
    return -logf(-logf(u));
}

// ---------------- reductions ----------------
__device__ __forceinline__ float blockSum(float v, float* rs) {
    int tid = threadIdx.x, w = tid >> 5, l = tid & 31, nw = blockDim.x >> 5;
#pragma unroll
    for (int o = 16; o > 0; o >>= 1) v += __shfl_xor_sync(~0u, v, o);
    if (l == 0) rs[w] = v;
    __syncthreads();
    if (w == 0) {
        float x = (l < nw) ? rs[l] : 0.0f;
#pragma unroll
        for (int o = 16; o > 0; o >>= 1) x += __shfl_xor_sync(~0u, x, o);
        if (l == 0) rs[0] = x;
    }
    __syncthreads();
    float r = rs[0]; __syncthreads(); return r;
}
__device__ __forceinline__ float blockMax(float v, float* rs) {
    int tid = threadIdx.x, w = tid >> 5, l = tid & 31, nw = blockDim.x >> 5;
#pragma unroll
    for (int o = 16; o > 0; o >>= 1) v = fmaxf(v, __shfl_xor_sync(~0u, v, o));
    if (l == 0) rs[w] = v;
    __syncthreads();
    if (w == 0) {
        float x = (l < nw) ? rs[l] : -INFINITY;
#pragma unroll
        for (int o = 16; o > 0; o >>= 1) x = fmaxf(x, __shfl_xor_sync(~0u, x, o));
        if (l == 0) rs[0] = x;
    }
    __syncthreads();
    float r = rs[0]; __syncthreads(); return r;
}
__device__ __forceinline__ void warpArgmax(float& v, int& idx) {
#pragma unroll
    for (int o = 16; o > 0; o >>= 1) {
        float ov = __shfl_xor_sync(~0u, v, o);
        int   oi = __shfl_xor_sync(~0u, idx, o);
        if (ov > v || (ov == v && oi < idx)) { v = ov; idx = oi; }
    }
}
__device__ __forceinline__ void blockArgmax(float& v, int& idx, float* rv, int* ri) {
    int tid = threadIdx.x, w = tid >> 5, l = tid & 31, nw = (blockDim.x + 31) >> 5;
    warpArgmax(v, idx);
    if (l == 0) { rv[w] = v; ri[w] = idx; }
    __syncthreads();
    if (w == 0) {
        float vv = (l < nw) ? rv[l] : -INFINITY;
        int   ii = (l < nw) ? ri[l] : 0x7fffffff;
        warpArgmax(vv, ii);
        if (l == 0) { rv[0] = vv; ri[0] = ii; }
    }
    __syncthreads();
    v = rv[0]; idx = ri[0]; __syncthreads();
}

// ---------------- precompute (proven) ----------------
__global__ void __launch_bounds__(1024) k_topk_cand() {
    __shared__ float vals[MM];
    __shared__ float rv[32]; __shared__ int ri[32];
    uint32_t ka, kb; tf2x32(0u, 7u, 0u, 0u, ka, kb);
    for (int i = threadIdx.x; i < MM; i += blockDim.x)
        vals[i] = gumbel_u32(rbits(ka, kb, (uint32_t)i));
    __syncthreads();
    for (int r = 0; r < CC; r++) {
        float bv = -INFINITY; int bi = 0x7fffffff;
        for (int i = threadIdx.x; i < MM; i += blockDim.x) {
            float v = vals[i];
            if (v > bv) { bv = v; bi = i; }
        }
        blockArgmax(bv, bi, rv, ri);
        if (threadIdx.x == 0) { g_cand[r] = bi; vals[bi] = -INFINITY; }
        __syncthreads();
    }
}

__global__ void __launch_bounds__(EE) k_bm(const float* __restrict__ emb,
                                           const float* __restrict__ s1w) {
    __shared__ float se[EE];
    int m = blockIdx.x, d = threadIdx.x;
    se[d] = emb[m * EE + d];
    __syncthreads();
    float acc = 0.0f;
#pragma unroll 8
    for (int e = 0; e < EE; e++) acc += se[e] * s1w[(EE + e) * EE + d];
    g_Bm[m * EE + d] = acc;
}

__global__ void __launch_bounds__(EE) k_a(const float* __restrict__ emb,
                                          const float* __restrict__ s1w) {
    __shared__ float se[EE];
    int c = blockIdx.x, d = threadIdx.x;
    se[d] = emb[g_cand[c] * EE + d];
    __syncthreads();
    float acc = 0.0f;
#pragma unroll 8
    for (int e = 0; e < EE; e++) acc += se[e] * s1w[e * EE + d];
    g_At[d * CC + c] = acc;
}

__global__ void __launch_bounds__(CC) k_selectp(const float* __restrict__ s1b,
                                                const float* __restrict__ s2w,
                                                const float* __restrict__ s2b) {
    __shared__ float sb[EE], sw[EE], sbm[EE];
    __shared__ float p[CC], sc[CC];
    __shared__ float rs[32], rv[32]; __shared__ int ri[32];
    int m = blockIdx.x, c = threadIdx.x;
    if (c < EE) { sb[c] = s1b[c]; sw[c] = s2w[c]; sbm[c] = g_Bm[m * EE + c]; }
    __syncthreads();
    float acc = 0.0f;
#pragma unroll 4
    for (int e = 0; e < EE; e++) {
        float t = g_At[e * CC + c] + sbm[e] + sb[e];
        t = (t >= 0.0f) ? t : 0.01f * t;
        acc += t * sw[e];
    }
    float logit = acc + s2b[0];
    float mx = blockMax(logit, rs);
    float ex = expf(logit - mx);
    float sm = blockSum(ex, rs);
    float pc = ex / sm;
    p[c] = pc;
    uint32_t ka, kb; tf2x32(0u, 7u, 0u, 1u, ka, kb);
    sc[c] = logf(pc) + gumbel_u32(rbits(ka, kb, (uint32_t)(m * CC + c)));
    __syncthreads();
    for (int s = 0; s < SS; s++) {
        float bv = sc[c]; int bi = c;
        blockArgmax(bv, bi, rv, ri);
        if (threadIdx.x == 0) {
            g_nlist[m * SS + s] = g_cand[bi];
            g_nprob[m * SS + s] = p[bi];
            sc[bi] = -INFINITY;
        }
        __syncthreads();
    }
}

// 4-row GEMV slice: NC cols at COL0, K reduce, 1024 threads; X rows stride XS.
#define GEMV4(W, LDN, COL0, X, XS, NC, K)                                   \
  {                                                                         \
    const int G_ = (NC) / 4, P_ = 1024 / G_, KC_ = (K) / P_;                \
    const int g_ = tid % G_, p_ = tid / G_;                                 \
    const float4* W4_ = (const float4*)(W) + ((COL0) >> 2) + g_;            \
    const int ld4_ = (LDN) >> 2;                                            \
    float4 a0_ = make_float4(0.f,0.f,0.f,0.f), a1_ = a0_, a2_ = a0_, a3_ = a0_; \
    int k_ = p_ * KC_;                                                      \
    _Pragma("unroll 8")                                                     \
    for (int kk_ = 0; kk_ < KC_; kk_++, k_++) {                             \
      float4 w4_ = W4_[(size_t)k_ * ld4_];                                  \
      fm4(a0_, (X)[k_], w4_);                                               \
      fm4(a1_, (X)[(XS) + k_], w4_);                                        \
      fm4(a2_, (X)[2 * (XS) + k_], w4_);                                    \
      fm4(a3_, (X)[3 * (XS) + k_], w4_);                                    \
    }                                                                       \
    scr4[p_ * G_ + g_] = a0_;                                               \
    scr4[1024 + p_ * G_ + g_] = a1_;                                        \
    scr4[2048 + p_ * G_ + g_] = a2_;                                        \
    scr4[3072 + p_ * G_ + g_] = a3_;                                        \
  }                                                                         \
  __syncthreads();

__device__ __forceinline__ float4 redSlice4(const float4* scr4, int r, int g, int G, int P) {
    float4 a = scr4[r * 1024 + g];
    for (int p = 1; p < P; p++) add4(a, scr4[r * 1024 + p * G + g]);
    return a;
}

// ---------------- main: 64 CTAs = 8 groups x 8 slices, 4 rows/group ----------------
__global__ void __launch_bounds__(1024) k_seq5(
    const int* __restrict__ marker, const float* __restrict__ timed,
    const float* __restrict__ maskd, const float* __restrict__ emb,
    const float* __restrict__ te_w, const float* __restrict__ te_b,
    const float* __restrict__ el_w, const float* __restrict__ el_b,
    const float* __restrict__ ml_w, const float* __restrict__ ml_b,
    const float* __restrict__ tl_w, const float* __restrict__ tl_b,
    const float* __restrict__ wq, const float* __restrict__ wk,
    const float* __restrict__ wv, const float* __restrict__ wo,
    const float* __restrict__ wo_b,
    const float* __restrict__ ln1s, const float* __restrict__ ln1b,
    const float* __restrict__ ff1w, const float* __restrict__ ff1b,
    const float* __restrict__ ff2w, const float* __restrict__ ff2b,
    const float* __restrict__ ln2s, const float* __restrict__ ln2b,
    float* __restrict__ out)
{
    const int tid = threadIdx.x;
    const int grp = blockIdx.x >> 3;
    const int slc = blockIdx.x & 7;
    const int col0 = slc * 64;       // D slice (= head slc)
    const int colF = slc * 256;      // DII slice
    const int r0 = grp * RPC;

    extern __shared__ float smb[];
    float4* scr4  = (float4*)smb;            // 4096 f4 = 16384 floats
    float* h1s    = smb + 16384;             // 8192 (4 rows x 2048)
    float* mds    = h1s + 8192;              // 2048 (4 x 512)
    float* x1s    = mds + 2048;              // 2048
    float* ctxs   = x1s + 2048;              // 2048
    float* sints  = ctxs + 2048;             // 512 (own row)
    float* qs     = sints + 512;             // 256 (4 rows x 64)
    float* scs    = qs + 256;                // 256 (4 rows x 64)
    float* vv     = scs + 256;               // 512 (4 rows x 128)
    float* s_prob = vv + 512;                // LP
    float* s_nrec = s_prob + LP;             // LNN
    int*   s_cand = (int*)(s_nrec + LNN);    // LP

    __shared__ float rs[32], rv[32]; __shared__ int ri[32];
    __shared__ float smw[SS]; __shared__ int snb[SS];
    __shared__ float sstat[8];
    __shared__ int sv_chosen;

    // ---- init (slices 0..3 own rows r0+slc) ----
    if (slc < RPC) {
        int r = r0 + slc;
        for (int j = tid; j < LP;  j += 1024) { s_prob[j] = 0.f; s_cand[j] = 0; }
        for (int j = tid; j < LNN; j += 1024) s_nrec[j] = 0.f;
        if (tid == 0) {
            int m0 = marker[r * TT]; float t0 = timed[r * TT];
            s_prob[0] = 1.f; s_cand[0] = m0; s_nrec[0] = 1.f;
            sv_chosen = 0;
            g_lm[r] = m0; g_ltm[r] = t0;
            out[0 * (BB * TT) + r * TT] = (float)m0;
            out[1 * (BB * TT) + r * TT] = t0;
            out[2 * (BB * TT) + r * TT] = maskd[r * TT];
            out[3 * (BB * TT) + r * TT] = 1.f;
            out[4 * (BB * TT) + r * TT] = 1.f;
        }
    }
    rowBarrier(grp);

    for (int i = 0; i < TMS; i++) {
        // ---- vvec (4 rows) + FULL md locally ----
        if (tid < 512) {
            int r2 = tid >> 7, e = tid & 127;
            int lmr = g_lm[r0 + r2]; float ltr = g_ltm[r0 + r2];
            vv[tid] = emb[lmr * EE + e] + 0.1f * (ltr * te_w[e] + te_b[e]);
        }
        __syncthreads();
        GEMV4(el_w, DD, 0, vv, 128, 512, 128)
        if (tid < 512) {
            int r2 = tid >> 7, g2 = tid & 127;
            float4 a = redSlice4(scr4, r2, g2, 128, 8);
            float4 bq = ((const float4*)el_b)[g2];
            a.x += bq.x; a.y += bq.y; a.z += bq.z; a.w += bq.w;
            a.x = (a.x >= 0.f) ? a.x : 0.01f * a.x;
            a.y = (a.y >= 0.f) ? a.y : 0.01f * a.y;
            a.z = (a.z >= 0.f) ? a.z : 0.01f * a.z;
            a.w = (a.w >= 0.f) ? a.w : 0.01f * a.w;
            ((float4*)mds)[r2 * 128 + g2] = a;
        }
        __syncthreads();

        // ---- q / k / v slices (head slc, 4 rows) ----
        GEMV4(wq, DD, col0, mds, 512, 64, 512)
        if (tid < 64) {
            int r2 = tid >> 4, g2 = tid & 15;
            ((float4*)qs)[r2 * 16 + g2] = redSlice4(scr4, r2, g2, 16, 64);
        }
        __syncthreads();
        GEMV4(wk, DD, col0, mds, 512, 64, 512)
        if (tid < 64) {
            int r2 = tid >> 4, g2 = tid & 15;
            int r = r0 + r2;
            ((float4*)g_kc)[(((size_t)(r * TMS + i) * DD + col0) >> 2) + g2] =
                redSlice4(scr4, r2, g2, 16, 64);
        }
        __syncthreads();
        GEMV4(wv, DD, col0, mds, 512, 64, 512)
        if (tid < 64) {
            int r2 = tid >> 4, g2 = tid & 15;
            int r = r0 + r2;
            ((float4*)g_vc)[(((size_t)(r * TMS + i) * DD + col0) >> 2) + g2] =
                redSlice4(scr4, r2, g2, 16, 64);
        }
        __syncthreads();

        // ---- attention (head slc, 4 rows) ----
        if (tid < 4 * (i + 1)) {
            int r2 = tid & 3, t = tid >> 2;
            int r = r0 + r2;
            const float4* kp = (const float4*)&g_kc[(size_t)(r * TMS + t) * DD + col0];
            const float4* qp = (const float4*)&qs[r2 * 64];
            float acc = 0.f;
#pragma unroll
            for (int d = 0; d < 16; d++) {
                float4 q4 = qp[d], k4 = kp[d];
                acc += q4.x * k4.x + q4.y * k4.y + q4.z * k4.z + q4.w * k4.w;
            }
            scs[r2 * 64 + t] = acc * 0.125f;
        }
        __syncthreads();
        if (tid < 4) {
            float* sp = &scs[tid * 64];
            float mx = -INFINITY;
            for (int t = 0; t <= i; t++) mx = fmaxf(mx, sp[t]);
            float sm = 0.f;
            for (int t = 0; t <= i; t++) { float e = expf(sp[t] - mx); sp[t] = e; sm += e; }
            for (int t = 0; t <= i; t++) sp[t] /= sm;
        }
        __syncthreads();
        if (tid < 256) {
            int r2 = tid >> 6, d = tid & 63;
            int r = r0 + r2;
            float acc = 0.f;
            for (int t = 0; t <= i; t++)
                acc += scs[r2 * 64 + t] * g_vc[(size_t)(r * TMS + t) * DD + col0 + d];
            g_ctx[r * DD + col0 + d] = acc;
        }
        rowBarrier(grp);   // A

        // ---- full ctx; wo slice + LN1 partial stats ----
        if (tid < 512) ((float4*)ctxs)[tid] = ((const float4*)g_ctx)[((size_t)r0 * DD >> 2) + tid];
        __syncthreads();
        GEMV4(wo, DD, col0, ctxs, 512, 64, 512)
        if (tid < 64) {
            int r2 = tid >> 4, g2 = tid & 15;
            int r = r0 + r2;
            float4 a = redSlice4(scr4, r2, g2, 16, 64);
            float4 bq = ((const float4*)wo_b)[(col0 >> 2) + g2];
            float4 m4 = ((const float4*)mds)[r2 * 128 + (col0 >> 2) + g2];
            float4 val;
            val.x = m4.x + a.x + bq.x; val.y = m4.y + a.y + bq.y;
            val.z = m4.z + a.z + bq.z; val.w = m4.w + a.w + bq.w;
            ((float4*)g_x1r)[(((size_t)r * DD + col0) >> 2) + g2] = val;
            float s1 = val.x + val.y + val.z + val.w;
            float s2 = val.x*val.x + val.y*val.y + val.z*val.z + val.w*val.w;
#pragma unroll
            for (int o = 8; o >= 1; o >>= 1) {
                s1 += __shfl_xor_sync(~0u, s1, o);
                s2 += __shfl_xor_sync(~0u, s2, o);
            }
            if (g2 == 0) {
                g_st1[r * 16 + slc * 2] = s1;
                g_st1[r * 16 + slc * 2 + 1] = s2;
            }
        }
        rowBarrier(grp);   // B

        // ---- LN1 -> x1s; ff1 slice ----
        if (tid < RPC) {
            int r = r0 + tid;
            float S1 = 0.f, S2 = 0.f;
#pragma unroll
            for (int s2i = 0; s2i < SLC; s2i++) {
                S1 += g_st1[r * 16 + s2i * 2];
                S2 += g_st1[r * 16 + s2i * 2 + 1];
            }
            float mn = S1 / (float)DD;
            float var = fmaxf(S2 / (float)DD - mn * mn, 0.f);
            sstat[tid * 2] = mn;
            sstat[tid * 2 + 1] = 1.f / sqrtf(var + 1e-5f);
        }
        __syncthreads();
        if (tid < 512) {
            int r2 = tid >> 7, c4 = tid & 127;
            float mn = sstat[r2 * 2], rsd = sstat[r2 * 2 + 1];
            float4 v4 = ((const float4*)g_x1r)[((size_t)r0 * DD >> 2) + tid];
            float4 g4 = ((const float4*)ln1s)[c4];
            float4 b4 = ((const float4*)ln1b)[c4];
            float4 o4;
            o4.x = (v4.x - mn) * rsd * g4.x + b4.x;
            o4.y = (v4.y - mn) * rsd * g4.y + b4.y;
            o4.z = (v4.z - mn) * rsd * g4.z + b4.z;
            o4.w = (v4.w - mn) * rsd * g4.w + b4.w;
            ((float4*)x1s)[tid] = o4;
        }
        __syncthreads();
        GEMV4(ff1w, DII, colF, x1s, 512, 256, 512)
        if (tid < 256) {
            int r2 = tid >> 6, g2 = tid & 63;
            int r = r0 + r2;
            float4 a = redSlice4(scr4, r2, g2, 64, 16);
            float4 b4 = ((const float4*)ff1b)[(colF >> 2) + g2];
            a.x = fmaxf(a.x + b4.x, 0.f); a.y = fmaxf(a.y + b4.y, 0.f);
            a.z = fmaxf(a.z + b4.z, 0.f); a.w = fmaxf(a.w + b4.w, 0.f);
            ((float4*)g_h1)[(((size_t)r * DII + colF) >> 2) + g2] = a;
        }
        rowBarrier(grp);   // C

        // ---- full h1 (4 rows); ff2 slice + LN2 partial stats ----
        ((float4*)h1s)[tid] = ((const float4*)g_h1)[((size_t)r0 * DII >> 2) + tid];
        ((float4*)h1s)[1024 + tid] = ((const float4*)g_h1)[((size_t)r0 * DII >> 2) + 1024 + tid];
        __syncthreads();
        GEMV4(ff2w, DD, col0, h1s, 2048, 64, 2048)
        if (tid < 64) {
            int r2 = tid >> 4, g2 = tid & 15;
            int r = r0 + r2;
            float4 a = redSlice4(scr4, r2, g2, 16, 64);
            float4 bq = ((const float4*)ff2b)[(col0 >> 2) + g2];
            float4 x4 = ((const float4*)x1s)[r2 * 128 + (col0 >> 2) + g2];
            float4 val;
            val.x = x4.x + a.x + bq.x; val.y = x4.y + a.y + bq.y;
            val.z = x4.z + a.z + bq.z; val.w = x4.w + a.w + bq.w;
            ((float4*)g_intr)[(((size_t)r * DD + col0) >> 2) + g2] = val;
            float s1 = val.x + val.y + val.z + val.w;
            float s2 = val.x*val.x + val.y*val.y + val.z*val.z + val.w*val.w;
#pragma unroll
            for (int o = 8; o >= 1; o >>= 1) {
                s1 += __shfl_xor_sync(~0u, s1, o);
                s2 += __shfl_xor_sync(~0u, s2, o);
            }
            if (g2 == 0) {
                g_st2[r * 16 + slc * 2] = s1;
                g_st2[r * 16 + slc * 2 + 1] = s2;
            }
        }
        rowBarrier(grp);   // D

        // ---- select (slices 0..3; row r0+slc) ----
        if (slc < RPC) {
            const int r = r0 + slc;
            const int lm = g_lm[r];
            const float lt = g_ltm[r];
            const int chosen = sv_chosen;

            if (tid == 0) {
                float S1 = 0.f, S2 = 0.f;
#pragma unroll
                for (int s2i = 0; s2i < SLC; s2i++) {
                    S1 += g_st2[r * 16 + s2i * 2];
                    S2 += g_st2[r * 16 + s2i * 2 + 1];
                }
                float mn = S1 / (float)DD;
                float var = fmaxf(S2 / (float)DD - mn * mn, 0.f);
                sstat[0] = mn;
                sstat[1] = 1.f / sqrtf(var + 1e-5f);
            }
            __syncthreads();
            if (tid < 128) {
                float mn = sstat[0], rsd = sstat[1];
                float4 v4 = ((const float4*)g_intr)[((size_t)r * DD >> 2) + tid];
                float4 g4 = ((const float4*)ln2s)[tid];
                float4 b4 = ((const float4*)ln2b)[tid];
                float4 o4;
                o4.x = (v4.x - mn) * rsd * g4.x + b4.x;
                o4.y = (v4.y - mn) * rsd * g4.y + b4.y;
                o4.z = (v4.z - mn) * rsd * g4.z + b4.z;
                o4.w = (v4.w - mn) * rsd * g4.w + b4.w;
                ((float4*)sints)[tid] = o4;
            }
            __syncthreads();

            float tv = 0.f, mv = 0.f;
            if (tid < DD) {
                tv = sints[tid] * tl_w[tid];
                mv = sints[tid] * ml_w[EE + tid];
            }
            float tdot = blockSum(tv, rs) + tl_b[0];
            float iml = blockSum(mv, rs);
            float nt = lt + (fmaxf(tdot, 0.f) + log1pf(expf(-fabsf(tdot))));

            if (tid < SS) {
                snb[tid] = g_nlist[lm * SS + tid];
                s_nrec[1 + i * SS + tid] = g_nprob[lm * SS + tid];
            }
            __syncthreads();
            if (tid < SS) {
                float acc = 0.f;
                const float4* ep = (const float4*)&emb[snb[tid] * EE];
                const float4* mw4 = (const float4*)ml_w;
#pragma unroll
                for (int e = 0; e < 32; e++) {
                    float4 a4 = ep[e], w4 = mw4[e];
                    acc += a4.x * w4.x + a4.y * w4.y + a4.z * w4.z + a4.w * w4.w;
                }
                smw[tid] = acc + iml + ml_b[0];
            }
            __syncthreads();
            if (tid < SS) {
                float v = smw[tid];
                float mx = v;
#pragma unroll
                for (int o = 16; o > 0; o >>= 1) mx = fmaxf(mx, __shfl_xor_sync(~0u, mx, o));
                float ex = expf(v - mx);
                float sm = ex;
#pragma unroll
                for (int o = 16; o > 0; o >>= 1) sm += __shfl_xor_sync(~0u, sm, o);
                float mp = ex / sm;
                float pc = s_prob[chosen];
                __syncwarp();
                float att = pc * mp;
                if (tid == 0) s_prob[chosen] = att;
                else {
                    s_prob[1 + i * (SS - 1) + tid - 1] = att;
                    s_cand[1 + i * (SS - 1) + tid - 1] = snb[tid];
                }
            }
            __syncthreads();

            uint32_t ka, kb;
            tf2x32(0u, 11u, 0u, (uint32_t)i, ka, kb);
            float bv = -INFINITY; int bi = 0x7fffffff;
            for (int j = tid; j < LP; j += 1024) {
                float z = logf(s_prob[j]) + gumbel_u32(rbits(ka, kb, (uint32_t)(r * LP + j)));
                if (z > bv) { bv = z; bi = j; }
            }
            blockArgmax(bv, bi, rv, ri);

            if (tid == 0) {
                int nc = bi, nm = s_cand[nc];
                sv_chosen = nc;
                g_lm[r] = nm; g_ltm[r] = nt;
                int o = r * TT + (i + 1);
                out[0 * (BB * TT) + o] = (float)nm;
                out[1 * (BB * TT) + o] = nt;
                out[2 * (BB * TT) + o] = (nt < 50.0f) ? 1.0f : 0.0f;
                out[3 * (BB * TT) + o] = s_nrec[nc];
                out[4 * (BB * TT) + o] = s_prob[nc];
            }
        }
        rowBarrier(grp);   // E
    }
}

extern "C" void kernel_launch(void* const* d_in, const int* in_sizes, int n_in,
                              void* d_out, int out_size) {
    const int*   marker = (const int*)  d_in[0];
    const float* timed  = (const float*)d_in[1];
    const float* maskd  = (const float*)d_in[2];
    const float* emb    = (const float*)d_in[3];
    const float* te_w   = (const float*)d_in[4];
    const float* te_b   = (const float*)d_in[5];
    const float* el_w   = (const float*)d_in[6];
    const float* el_b   = (const float*)d_in[7];
    const float* s1_w   = (const float*)d_in[8];
    const float* s1_b   = (const float*)d_in[9];
    const float* s2_w   = (const float*)d_in[10];
    const float* s2_b   = (const float*)d_in[11];
    const float* ml_w   = (const float*)d_in[12];
    const float* ml_b   = (const float*)d_in[13];
    const float* tl_w   = (const float*)d_in[14];
    const float* tl_b   = (const float*)d_in[15];
    const float* wq     = (const float*)d_in[16];
    const float* wk     = (const float*)d_in[17];
    const float* wv     = (const float*)d_in[18];
    const float* wo     = (const float*)d_in[19];
    const float* wo_b   = (const float*)d_in[20];
    const float* ln1_s  = (const float*)d_in[21];
    const float* ln1_b  = (const float*)d_in[22];
    const float* ff1_w  = (const float*)d_in[23];
    const float* ff1_b  = (const float*)d_in[24];
    const float* ff2_w  = (const float*)d_in[25];
    const float* ff2_b  = (const float*)d_in[26];
    const float* ln2_s  = (const float*)d_in[27];
    const float* ln2_b  = (const float*)d_in[28];
    float* out = (float*)d_out;

    static int inited = 0;
    if (!inited) {
        cudaFuncSetAttribute(k_seq5, cudaFuncAttributeMaxDynamicSharedMemorySize,
                             DYN_BYTES);
        inited = 1;
    }

    k_topk_cand<<<1, 1024>>>();
    k_bm<<<MM, EE>>>(emb, s1_w);
    k_a<<<CC, EE>>>(emb, s1_w);
    k_selectp<<<MM, CC>>>(s1_b, s2_w, s2_b);
    k_seq5<<<NG * SLC, 1024, DYN_BYTES>>>(
        marker, timed, maskd, emb, te_w, te_b, el_w, el_b, ml_w, ml_b,
        tl_w, tl_b, wq, wk, wv, wo, wo_b, ln1_s, ln1_b,
        ff1_w, ff1_b, ff2_w, ff2_b, ln2_s, ln2_b, out);
}

// round 17
// speedup vs baseline: 2.2344x; 1.0202x over previous
#include <cuda_runtime.h>
#include <math.h>
#include <stdint.h>

#define MM 5000
#define EE 128
#define DD 512
#define DII 2048
#define CC 256
#define SS 32
#define BB 32
#define TT 64
#define TMS 63
#define LP 1954
#define LNN 2017
#define NG 8         // row groups (4 rows each)
#define SLC 8        // CTAs (slices) per group
#define RPC 4        // rows per group

#define DYN_FLOATS (16384 + 8192 + 2048 + 2048 + 2048 + 512 + 256 + 256 + 512 + LP + LNN + LP)
#define DYN_BYTES (DYN_FLOATS * 4)

// ---------------- device state ----------------
__device__ int   g_cand[CC];
__device__ float g_At[EE * CC];
__device__ float g_Bm[MM * EE];
__device__ int   g_nlist[MM * SS];
__device__ float g_nprob[MM * SS];

__device__ float g_kc[BB * TMS * DD];
__device__ float g_vc[BB * TMS * DD];
__device__ float g_ctx[BB * DD];
__device__ float g_x1r[BB * DD];
__device__ float g_h1[BB * DII];
__device__ float g_intr[BB * DD];
__device__ float g_st1[BB * 16];
__device__ float g_st2[BB * 16];
__device__ int   g_lm[BB];
__device__ float g_ltm[BB];

__device__ int          g_rcnt[NG * 32];
__device__ volatile int g_rgen[NG * 32];

__device__ __forceinline__ void rowBarrier(int grp) {
    __syncthreads();
    if (threadIdx.x == 0) {
        volatile int* genp = &g_rgen[grp * 32];
        int gen = *genp;
        __threadfence();
        if (atomicAdd(&g_rcnt[grp * 32], 1) == SLC - 1) {
            g_rcnt[grp * 32] = 0;
            __threadfence();
            *genp = gen + 1;
        } else {
            while (*genp == gen) __nanosleep(32);
        }
        __threadfence();
    }
    __syncthreads();
}

__device__ __forceinline__ void add4(float4& a, const float4& b) {
    a.x += b.x; a.y += b.y; a.z += b.z; a.w += b.w;
}
__device__ __forceinline__ void fm4(float4& a, float s, const float4& b) {
    a.x += s * b.x; a.y += s * b.y; a.z += s * b.z; a.w += s * b.w;
}

// ---------------- threefry (JAX partitionable) ----------------
__device__ __forceinline__ void tf2x32(uint32_t k0, uint32_t k1, uint32_t x0, uint32_t x1,
                                       uint32_t& o0, uint32_t& o1) {
    uint32_t k2 = k0 ^ k1 ^ 0x1BD11BDAu;
    x0 += k0; x1 += k1;
#define TF_R(r) { x0 += x1; x1 = (x1 << r) | (x1 >> (32 - r)); x1 ^= x0; }
    TF_R(13) TF_R(15) TF_R(26) TF_R(6)   x0 += k1; x1 += k2 + 1u;
    TF_R(17) TF_R(29) TF_R(16) TF_R(24)  x0 += k2; x1 += k0 + 2u;
    TF_R(13) TF_R(15) TF_R(26) TF_R(6)   x0 += k0; x1 += k1 + 3u;
    TF_R(17) TF_R(29) TF_R(16) TF_R(24)  x0 += k1; x1 += k2 + 4u;
    TF_R(13) TF_R(15) TF_R(26) TF_R(6)   x0 += k2; x1 += k0 + 5u;
#undef TF_R
    o0 = x0; o1 = x1;
}
__device__ __forceinline__ uint32_t rbits(uint32_t k0, uint32_t k1, uint32_t idx) {
    uint32_t a, b; tf2x32(k0, k1, 0u, idx, a, b); return a ^ b;
}
__device__ __forceinline__ float gumbel_u32(uint32_t bits) {
    const float tiny = 1.17549435e-38f;
    float f = __uint_as_float((bits >> 9) | 0x3f800000u) - 1.0f;
    float u = fmaxf(tiny, f + tiny);
    return -logf(-logf(u));
}

// ---------------- reductions ----------------
__device__ __forceinline__ float blockSum(float v, float* rs) {
    int tid = threadIdx.x, w = tid >> 5, l = tid & 31, nw = blockDim.x >> 5;
#pragma unroll
    for (int o = 16; o > 0; o >>= 1) v += __shfl_xor_sync(~0u, v, o);
    if (l == 0) rs[w] = v;
    __syncthreads();
    if (w == 0) {
        float x = (l < nw) ? rs[l] : 0.0f;
#pragma unroll
        for (int o = 16; o > 0; o >>= 1) x += __shfl_xor_sync(~0u, x, o);
        if (l == 0) rs[0] = x;
    }
    __syncthreads();
    float r = rs[0]; __syncthreads(); return r;
}
__device__ __forceinline__ float blockMax(float v, float* rs) {
    int tid = threadIdx.x, w = tid >> 5, l = tid & 31, nw = blockDim.x >> 5;
#pragma unroll
    for (int o = 16; o > 0; o >>= 1) v = fmaxf(v, __shfl_xor_sync(~0u, v, o));
    if (l == 0) rs[w] = v;
    __syncthreads();
    if (w == 0) {
        float x = (l < nw) ? rs[l] : -INFINITY;
#pragma unroll
        for (int o = 16; o > 0; o >>= 1) x = fmaxf(x, __shfl_xor_sync(~0u, x, o));
        if (l == 0) rs[0] = x;
    }
    __syncthreads();
    float r = rs[0]; __syncthreads(); return r;
}
__device__ __forceinline__ void warpArgmax(float& v, int& idx) {
#pragma unroll
    for (int o = 16; o > 0; o >>= 1) {
        float ov = __shfl_xor_sync(~0u, v, o);
        int   oi = __shfl_xor_sync(~0u, idx, o);
        if (ov > v || (ov == v && oi < idx)) { v = ov; idx = oi; }
    }
}
__device__ __forceinline__ void blockArgmax(float& v, int& idx, float* rv, int* ri) {
    int tid = threadIdx.x, w = tid >> 5, l = tid & 31, nw = (blockDim.x + 31) >> 5;
    warpArgmax(v, idx);
    if (l == 0) { rv[w] = v; ri[w] = idx; }
    __syncthreads();
    if (w == 0) {
        float vv = (l < nw) ? rv[l] : -INFINITY;
        int   ii = (l < nw) ? ri[l] : 0x7fffffff;
        warpArgmax(vv, ii);
        if (l == 0) { rv[0] = vv; ri[0] = ii; }
    }
    __syncthreads();
    v = rv[0]; idx = ri[0]; __syncthreads();
}

// ---------------- precompute ----------------
__global__ void __launch_bounds__(1024) k_topk_cand() {
    __shared__ float vals[MM];
    __shared__ float rv[32]; __shared__ int ri[32];
    uint32_t ka, kb; tf2x32(0u, 7u, 0u, 0u, ka, kb);
    for (int i = threadIdx.x; i < MM; i += blockDim.x)
        vals[i] = gumbel_u32(rbits(ka, kb, (uint32_t)i));
    __syncthreads();
    for (int r = 0; r < CC; r++) {
        float bv = -INFINITY; int bi = 0x7fffffff;
        for (int i = threadIdx.x; i < MM; i += blockDim.x) {
            float v = vals[i];
            if (v > bv) { bv = v; bi = i; }
        }
        blockArgmax(bv, bi, rv, ri);
        if (threadIdx.x == 0) { g_cand[r] = bi; vals[bi] = -INFINITY; }
        __syncthreads();
    }
}

// tiled Bm: 64 markers per block, s1w[E:] cached in smem once
__global__ void __launch_bounds__(256) k_bm2(const float* __restrict__ emb,
                                             const float* __restrict__ s1w) {
    extern __shared__ float sw[];         // 128*128 floats = 64KB
    __shared__ float se[2][EE];
    int tid = threadIdx.x;
    for (int j = tid; j < EE * EE; j += 256)
        sw[j] = s1w[(EE + (j >> 7)) * EE + (j & 127)];
    __syncthreads();
    int m0 = blockIdx.x * 64;
    int d = tid & 127, rr = tid >> 7;
    for (int it = 0; it < 32; it++) {
        int m = m0 + it * 2 + rr;
        if (m < MM) se[rr][d] = emb[m * EE + d];
        __syncthreads();
        if (m < MM) {
            float acc = 0.0f;
#pragma unroll 8
            for (int e = 0; e < EE; e++) acc += se[rr][e] * sw[e * EE + d];
            g_Bm[m * EE + d] = acc;
        }
        __syncthreads();
    }
}

__global__ void __launch_bounds__(EE) k_a(const float* __restrict__ emb,
                                          const float* __restrict__ s1w) {
    __shared__ float se[EE];
    int c = blockIdx.x, d = threadIdx.x;
    se[d] = emb[g_cand[c] * EE + d];
    __syncthreads();
    float acc = 0.0f;
#pragma unroll 8
    for (int e = 0; e < EE; e++) acc += se[e] * s1w[e * EE + d];
    g_At[d * CC + c] = acc;
}

__global__ void __launch_bounds__(CC) k_selectp(const float* __restrict__ s1b,
                                                const float* __restrict__ s2w,
                                                const float* __restrict__ s2b) {
    __shared__ float sb[EE], sw[EE], sbm[EE];
    __shared__ float p[CC], sc[CC];
    __shared__ float rs[32];
    int m = blockIdx.x, c = threadIdx.x;
    if (c < EE) { sb[c] = s1b[c]; sw[c] = s2w[c]; sbm[c] = g_Bm[m * EE + c]; }
    __syncthreads();
    float acc = 0.0f;
#pragma unroll 4
    for (int e = 0; e < EE; e++) {
        float t = g_At[e * CC + c] + sbm[e] + sb[e];
        t = (t >= 0.0f) ? t : 0.01f * t;
        acc += t * sw[e];
    }
    float logit = acc + s2b[0];
    float mx = blockMax(logit, rs);
    float ex = expf(logit - mx);
    float sm = blockSum(ex, rs);
    float pc = ex / sm;
    p[c] = pc;
    uint32_t ka, kb; tf2x32(0u, 7u, 0u, 1u, ka, kb);
    sc[c] = logf(pc) + gumbel_u32(rbits(ka, kb, (uint32_t)(m * CC + c)));
    __syncthreads();
    // single-warp register-resident top-32 (no block syncs)
    if (c < 32) {
        float v[8];
#pragma unroll
        for (int j = 0; j < 8; j++) v[j] = sc[c + 32 * j];
        for (int s = 0; s < SS; s++) {
            float bv = v[0]; int bj = 0;
#pragma unroll
            for (int j = 1; j < 8; j++) if (v[j] > bv) { bv = v[j]; bj = j; }
            float wv = bv; int wi = c + 32 * bj;
            warpArgmax(wv, wi);
            if (c == (wi & 31)) v[wi >> 5] = -INFINITY;
            if (c == 0) {
                g_nlist[m * SS + s] = g_cand[wi];
                g_nprob[m * SS + s] = p[wi];
            }
        }
    }
}

// 4-row GEMV slice: NC cols at COL0, K reduce, 1024 threads; X rows stride XS.
#define GEMV4(W, LDN, COL0, X, XS, NC, K)                                   \
  {                                                                         \
    const int G_ = (NC) / 4, P_ = 1024 / G_, KC_ = (K) / P_;                \
    const int g_ = tid % G_, p_ = tid / G_;                                 \
    const float4* W4_ = (const float4*)(W) + ((COL0) >> 2) + g_;            \
    const int ld4_ = (LDN) >> 2;                                            \
    float4 a0_ = make_float4(0.f,0.f,0.f,0.f), a1_ = a0_, a2_ = a0_, a3_ = a0_; \
    int k_ = p_ * KC_;                                                      \
    _Pragma("unroll 8")                                                     \
    for (int kk_ = 0; kk_ < KC_; kk_++, k_++) {                             \
      float4 w4_ = W4_[(size_t)k_ * ld4_];                                  \
      fm4(a0_, (X)[k_], w4_);                                               \
      fm4(a1_, (X)[(XS) + k_], w4_);                                        \
      fm4(a2_, (X)[2 * (XS) + k_], w4_);                                    \
      fm4(a3_, (X)[3 * (XS) + k_], w4_);                                    \
    }                                                                       \
    scr4[p_ * G_ + g_] = a0_;                                               \
    scr4[1024 + p_ * G_ + g_] = a1_;                                        \
    scr4[2048 + p_ * G_ + g_] = a2_;                                        \
    scr4[3072 + p_ * G_ + g_] = a3_;                                        \
  }                                                                         \
  __syncthreads();

__device__ __forceinline__ float4 redSlice4(const float4* scr4, int r, int g, int G, int P) {
    float4 a = scr4[r * 1024 + g];
    for (int p = 1; p < P; p++) add4(a, scr4[r * 1024 + p * G + g]);
    return a;
}

// ---------------- main: 64 CTAs = 8 groups x 8 slices, 4 rows/group ----------------
__global__ void __launch_bounds__(1024) k_seq5(
    const int* __restrict__ marker, const float* __restrict__ timed,
    const float* __restrict__ maskd, const float* __restrict__ emb,
    const float* __restrict__ te_w, const float* __restrict__ te_b,
    const float* __restrict__ el_w, const float* __restrict__ el_b,
    const float* __restrict__ ml_w, const float* __restrict__ ml_b,
    const float* __restrict__ tl_w, const float* __restrict__ tl_b,
    const float* __restrict__ wq, const float* __restrict__ wk,
    const float* __restrict__ wv, const float* __restrict__ wo,
    const float* __restrict__ wo_b,
    const float* __restrict__ ln1s, const float* __restrict__ ln1b,
    const float* __restrict__ ff1w, const float* __restrict__ ff1b,
    const float* __restrict__ ff2w, const float* __restrict__ ff2b,
    const float* __restrict__ ln2s, const float* __restrict__ ln2b,
    float* __restrict__ out)
{
    const int tid = threadIdx.x;
    const int grp = blockIdx.x >> 3;
    const int slc = blockIdx.x & 7;
    const int col0 = slc * 64;
    const int colF = slc * 256;
    const int r0 = grp * RPC;

    extern __shared__ float smb[];
    float4* scr4  = (float4*)smb;
    float* h1s    = smb + 16384;
    float* mds    = h1s + 8192;
    float* x1s    = mds + 2048;
    float* ctxs   = x1s + 2048;
    float* sints  = ctxs + 2048;
    float* qs     = sints + 512;
    float* scs    = qs + 256;
    float* vv     = scs + 256;
    float* s_prob = vv + 512;
    float* s_nrec = s_prob + LP;
    int*   s_cand = (int*)(s_nrec + LNN);

    __shared__ float rs[32], rv[32]; __shared__ int ri[32];
    __shared__ float smw[SS]; __shared__ int snb[SS];
    __shared__ float sstat[8];
    __shared__ int sv_chosen;

    if (slc < RPC) {
        int r = r0 + slc;
        for (int j = tid; j < LP;  j += 1024) { s_prob[j] = 0.f; s_cand[j] = 0; }
        for (int j = tid; j < LNN; j += 1024) s_nrec[j] = 0.f;
        if (tid == 0) {
            int m0 = marker[r * TT]; float t0 = timed[r * TT];
            s_prob[0] = 1.f; s_cand[0] = m0; s_nrec[0] = 1.f;
            sv_chosen = 0;
            g_lm[r] = m0; g_ltm[r] = t0;
            out[0 * (BB * TT) + r * TT] = (float)m0;
            out[1 * (BB * TT) + r * TT] = t0;
            out[2 * (BB * TT) + r * TT] = maskd[r * TT];
            out[3 * (BB * TT) + r * TT] = 1.f;
            out[4 * (BB * TT) + r * TT] = 1.f;
        }
    }
    rowBarrier(grp);

    for (int i = 0; i < TMS; i++) {
        if (tid < 512) {
            int r2 = tid >> 7, e = tid & 127;
            int lmr = g_lm[r0 + r2]; float ltr = g_ltm[r0 + r2];
            vv[tid] = emb[lmr * EE + e] + 0.1f * (ltr * te_w[e] + te_b[e]);
        }
        __syncthreads();
        GEMV4(el_w, DD, 0, vv, 128, 512, 128)
        if (tid < 512) {
            int r2 = tid >> 7, g2 = tid & 127;
            float4 a = redSlice4(scr4, r2, g2, 128, 8);
            float4 bq = ((const float4*)el_b)[g2];
            a.x += bq.x; a.y += bq.y; a.z += bq.z; a.w += bq.w;
            a.x = (a.x >= 0.f) ? a.x : 0.01f * a.x;
            a.y = (a.y >= 0.f) ? a.y : 0.01f * a.y;
            a.z = (a.z >= 0.f) ? a.z : 0.01f * a.z;
            a.w = (a.w >= 0.f) ? a.w : 0.01f * a.w;
            ((float4*)mds)[r2 * 128 + g2] = a;
        }
        __syncthreads();

        GEMV4(wq, DD, col0, mds, 512, 64, 512)
        if (tid < 64) {
            int r2 = tid >> 4, g2 = tid & 15;
            ((float4*)qs)[r2 * 16 + g2] = redSlice4(scr4, r2, g2, 16, 64);
        }
        __syncthreads();
        GEMV4(wk, DD, col0, mds, 512, 64, 512)
        if (tid < 64) {
            int r2 = tid >> 4, g2 = tid & 15;
            int r = r0 + r2;
            ((float4*)g_kc)[(((size_t)(r * TMS + i) * DD + col0) >> 2) + g2] =
                redSlice4(scr4, r2, g2, 16, 64);
        }
        __syncthreads();
        GEMV4(wv, DD, col0, mds, 512, 64, 512)
        if (tid < 64) {
            int r2 = tid >> 4, g2 = tid & 15;
            int r = r0 + r2;
            ((float4*)g_vc)[(((size_t)(r * TMS + i) * DD + col0) >> 2) + g2] =
                redSlice4(scr4, r2, g2, 16, 64);
        }
        __syncthreads();

        if (tid < 4 * (i + 1)) {
            int r2 = tid & 3, t = tid >> 2;
            int r = r0 + r2;
            const float4* kp = (const float4*)&g_kc[(size_t)(r * TMS + t) * DD + col0];
            const float4* qp = (const float4*)&qs[r2 * 64];
            float acc = 0.f;
#pragma unroll
            for (int d = 0; d < 16; d++) {
                float4 q4 = qp[d], k4 = kp[d];
                acc += q4.x * k4.x + q4.y * k4.y + q4.z * k4.z + q4.w * k4.w;
            }
            scs[r2 * 64 + t] = acc * 0.125f;
        }
        __syncthreads();
        if (tid < 4) {
            float* sp = &scs[tid * 64];
            float mx = -INFINITY;
            for (int t = 0; t <= i; t++) mx = fmaxf(mx, sp[t]);
            float sm = 0.f;
            for (int t = 0; t <= i; t++) { float e = expf(sp[t] - mx); sp[t] = e; sm += e; }
            for (int t = 0; t <= i; t++) sp[t] /= sm;
        }
        __syncthreads();
        if (tid < 256) {
            int r2 = tid >> 6, d = tid & 63;
            int r = r0 + r2;
            float acc = 0.f;
            for (int t = 0; t <= i; t++)
                acc += scs[r2 * 64 + t] * g_vc[(size_t)(r * TMS + t) * DD + col0 + d];
            g_ctx[r * DD + col0 + d] = acc;
        }
        rowBarrier(grp);   // A

        if (tid < 512) ((float4*)ctxs)[tid] = ((const float4*)g_ctx)[((size_t)r0 * DD >> 2) + tid];
        __syncthreads();
        GEMV4(wo, DD, col0, ctxs, 512, 64, 512)
        if (tid < 64) {
            int r2 = tid >> 4, g2 = tid & 15;
            int r = r0 + r2;
            float4 a = redSlice4(scr4, r2, g2, 16, 64);
            float4 bq = ((const float4*)wo_b)[(col0 >> 2) + g2];
            float4 m4 = ((const float4*)mds)[r2 * 128 + (col0 >> 2) + g2];
            float4 val;
            val.x = m4.x + a.x + bq.x; val.y = m4.y + a.y + bq.y;
            val.z = m4.z + a.z + bq.z; val.w = m4.w + a.w + bq.w;
            ((float4*)g_x1r)[(((size_t)r * DD + col0) >> 2) + g2] = val;
            float s1 = val.x + val.y + val.z + val.w;
            float s2 = val.x*val.x + val.y*val.y + val.z*val.z + val.w*val.w;
#pragma unroll
            for (int o = 8; o >= 1; o >>= 1) {
                s1 += __shfl_xor_sync(~0u, s1, o);
                s2 += __shfl_xor_sync(~0u, s2, o);
            }
            if (g2 == 0) {
                g_st1[r * 16 + slc * 2] = s1;
                g_st1[r * 16 + slc * 2 + 1] = s2;
            }
        }
        rowBarrier(grp);   // B

        if (tid < RPC) {
            int r = r0 + tid;
            float S1 = 0.f, S2 = 0.f;
#pragma unroll
            for (int s2i = 0; s2i < SLC; s2i++) {
                S1 += g_st1[r * 16 + s2i * 2];
                S2 += g_st1[r * 16 + s2i * 2 + 1];
            }
            float mn = S1 / (float)DD;
            float var = fmaxf(S2 / (float)DD - mn * mn, 0.f);
            sstat[tid * 2] = mn;
            sstat[tid * 2 + 1] = 1.f / sqrtf(var + 1e-5f);
        }
        __syncthreads();
        if (tid < 512) {
            int r2 = tid >> 7, c4 = tid & 127;
            float mn = sstat[r2 * 2], rsd = sstat[r2 * 2 + 1];
            float4 v4 = ((const float4*)g_x1r)[((size_t)r0 * DD >> 2) + tid];
            float4 g4 = ((const float4*)ln1s)[c4];
            float4 b4 = ((const float4*)ln1b)[c4];
            float4 o4;
            o4.x = (v4.x - mn) * rsd * g4.x + b4.x;
            o4.y = (v4.y - mn) * rsd * g4.y + b4.y;
            o4.z = (v4.z - mn) * rsd * g4.z + b4.z;
            o4.w = (v4.w - mn) * rsd * g4.w + b4.w;
            ((float4*)x1s)[tid] = o4;
        }
        __syncthreads();
        GEMV4(ff1w, DII, colF, x1s, 512, 256, 512)
        if (tid < 256) {
            int r2 = tid >> 6, g2 = tid & 63;
            int r = r0 + r2;
            float4 a = redSlice4(scr4, r2, g2, 64, 16);
            float4 b4 = ((const float4*)ff1b)[(colF >> 2) + g2];
            a.x = fmaxf(a.x + b4.x, 0.f); a.y = fmaxf(a.y + b4.y, 0.f);
            a.z = fmaxf(a.z + b4.z, 0.f); a.w = fmaxf(a.w + b4.w, 0.f);
            ((float4*)g_h1)[(((size_t)r * DII + colF) >> 2) + g2] = a;
        }
        rowBarrier(grp);   // C

        ((float4*)h1s)[tid] = ((const float4*)g_h1)[((size_t)r0 * DII >> 2) + tid];
        ((float4*)h1s)[1024 + tid] = ((const float4*)g_h1)[((size_t)r0 * DII >> 2) + 1024 + tid];
        __syncthreads();
        GEMV4(ff2w, DD, col0, h1s, 2048, 64, 2048)
        if (tid < 64) {
            int r2 = tid >> 4, g2 = tid & 15;
            int r = r0 + r2;
            float4 a = redSlice4(scr4, r2, g2, 16, 64);
            float4 bq = ((const float4*)ff2b)[(col0 >> 2) + g2];
            float4 x4 = ((const float4*)x1s)[r2 * 128 + (col0 >> 2) + g2];
            float4 val;
            val.x = x4.x + a.x + bq.x; val.y = x4.y + a.y + bq.y;
            val.z = x4.z + a.z + bq.z; val.w = x4.w + a.w + bq.w;
            ((float4*)g_intr)[(((size_t)r * DD + col0) >> 2) + g2] = val;
            float s1 = val.x + val.y + val.z + val.w;
            float s2 = val.x*val.x + val.y*val.y + val.z*val.z + val.w*val.w;
#pragma unroll
            for (int o = 8; o >= 1; o >>= 1) {
                s1 += __shfl_xor_sync(~0u, s1, o);
                s2 += __shfl_xor_sync(~0u, s2, o);
            }
            if (g2 == 0) {
                g_st2[r * 16 + slc * 2] = s1;
                g_st2[r * 16 + slc * 2 + 1] = s2;
            }
        }
        rowBarrier(grp);   // D

        if (slc < RPC) {
            const int r = r0 + slc;
            const int lm = g_lm[r];
            const float lt = g_ltm[r];
            const int chosen = sv_chosen;

            if (tid == 0) {
                float S1 = 0.f, S2 = 0.f;
#pragma unroll
                for (int s2i = 0; s2i < SLC; s2i++) {
                    S1 += g_st2[r * 16 + s2i * 2];
                    S2 += g_st2[r * 16 + s2i * 2 + 1];
                }
                float mn = S1 / (float)DD;
                float var = fmaxf(S2 / (float)DD - mn * mn, 0.f);
                sstat[0] = mn;
                sstat[1] = 1.f / sqrtf(var + 1e-5f);
            }
            __syncthreads();
            if (tid < 128) {
                float mn = sstat[0], rsd = sstat[1];
                float4 v4 = ((const float4*)g_intr)[((size_t)r * DD >> 2) + tid];
                float4 g4 = ((const float4*)ln2s)[tid];
                float4 b4 = ((const float4*)ln2b)[tid];
                float4 o4;
                o4.x = (v4.x - mn) * rsd * g4.x + b4.x;
                o4.y = (v4.y - mn) * rsd * g4.y + b4.y;
                o4.z = (v4.z - mn) * rsd * g4.z + b4.z;
                o4.w = (v4.w - mn) * rsd * g4.w + b4.w;
                ((float4*)sints)[tid] = o4;
            }
            __syncthreads();

            float tv = 0.f, mv = 0.f;
            if (tid < DD) {
                tv = sints[tid] * tl_w[tid];
                mv = sints[tid] * ml_w[EE + tid];
            }
            float tdot = blockSum(tv, rs) + tl_b[0];
            float iml = blockSum(mv, rs);
            float nt = lt + (fmaxf(tdot, 0.f) + log1pf(expf(-fabsf(tdot))));

            if (tid < SS) {
                snb[tid] = g_nlist[lm * SS + tid];
                s_nrec[1 + i * SS + tid] = g_nprob[lm * SS + tid];
            }
            __syncthreads();
            if (tid < SS) {
                float acc = 0.f;
                const float4* ep = (const float4*)&emb[snb[tid] * EE];
                const float4* mw4 = (const float4*)ml_w;
#pragma unroll
                for (int e = 0; e < 32; e++) {
                    float4 a4 = ep[e], w4 = mw4[e];
                    acc += a4.x * w4.x + a4.y * w4.y + a4.z * w4.z + a4.w * w4.w;
                }
                smw[tid] = acc + iml + ml_b[0];
            }
            __syncthreads();
            if (tid < SS) {
                float v = smw[tid];
                float mx = v;
#pragma unroll
                for (int o = 16; o > 0; o >>= 1) mx = fmaxf(mx, __shfl_xor_sync(~0u, mx, o));
                float ex = expf(v - mx);
                float sm = ex;
#pragma unroll
                for (int o = 16; o > 0; o >>= 1) sm += __shfl_xor_sync(~0u, sm, o);
                float mp = ex / sm;
                float pc = s_prob[chosen];
                __syncwarp();
                float att = pc * mp;
                if (tid == 0) s_prob[chosen] = att;
                else {
                    s_prob[1 + i * (SS - 1) + tid - 1] = att;
                    s_cand[1 + i * (SS - 1) + tid - 1] = snb[tid];
                }
            }
            __syncthreads();

            uint32_t ka, kb;
            tf2x32(0u, 11u, 0u, (uint32_t)i, ka, kb);
            float bv = -INFINITY; int bi = 0x7fffffff;
            for (int j = tid; j < LP; j += 1024) {
                float z = logf(s_prob[j]) + gumbel_u32(rbits(ka, kb, (uint32_t)(r * LP + j)));
                if (z > bv) { bv = z; bi = j; }
            }
            blockArgmax(bv, bi, rv, ri);

            if (tid == 0) {
                int nc = bi, nm = s_cand[nc];
                sv_chosen = nc;
                g_lm[r] = nm; g_ltm[r] = nt;
                int o = r * TT + (i + 1);
                out[0 * (BB * TT) + o] = (float)nm;
                out[1 * (BB * TT) + o] = nt;
                out[2 * (BB * TT) + o] = (nt < 50.0f) ? 1.0f : 0.0f;
                out[3 * (BB * TT) + o] = s_nrec[nc];
                out[4 * (BB * TT) + o] = s_prob[nc];
            }
        }
        rowBarrier(grp);   // E
    }
}

extern "C" void kernel_launch(void* const* d_in, const int* in_sizes, int n_in,
                              void* d_out, int out_size) {
    const int*   marker = (const int*)  d_in[0];
    const float* timed  = (const float*)d_in[1];
    const float* maskd  = (const float*)d_in[2];
    const float* emb    = (const float*)d_in[3];
    const float* te_w   = (const float*)d_in[4];
    const float* te_b   = (const float*)d_in[5];
    const float* el_w   = (const float*)d_in[6];
    const float* el_b   = (const float*)d_in[7];
    const float* s1_w   = (const float*)d_in[8];
    const float* s1_b   = (const float*)d_in[9];
    const float* s2_w   = (const float*)d_in[10];
    const float* s2_b   = (const float*)d_in[11];
    const float* ml_w   = (const float*)d_in[12];
    const float* ml_b   = (const float*)d_in[13];
    const float* tl_w   = (const float*)d_in[14];
    const float* tl_b   = (const float*)d_in[15];
    const float* wq     = (const float*)d_in[16];
    const float* wk     = (const float*)d_in[17];
    const float* wv     = (const float*)d_in[18];
    const float* wo     = (const float*)d_in[19];
    const float* wo_b   = (const float*)d_in[20];
    const float* ln1_s  = (const float*)d_in[21];
    const float* ln1_b  = (const float*)d_in[22];
    const float* ff1_w  = (const float*)d_in[23];
    const float* ff1_b  = (const float*)d_in[24];
    const float* ff2_w  = (const float*)d_in[25];
    const float* ff2_b  = (const float*)d_in[26];
    const float* ln2_s  = (const float*)d_in[27];
    const float* ln2_b  = (const float*)d_in[28];
    float* out = (float*)d_out;

    static int inited = 0;
    if (!inited) {
        cudaFuncSetAttribute(k_seq5, cudaFuncAttributeMaxDynamicSharedMemorySize,
                             DYN_BYTES);
        cudaFuncSetAttribute(k_bm2, cudaFuncAttributeMaxDynamicSharedMemorySize,
                             EE * EE * 4);
        inited = 1;
    }

    k_topk_cand<<<1, 1024>>>();
    k_bm2<<<(MM + 63) / 64, 256, EE * EE * 4>>>(emb, s1_w);
    k_a<<<CC, EE>>>(emb, s1_w);
    k_selectp<<<MM, CC>>>(s1_b, s2_w, s2_b);
    k_seq5<<<NG * SLC, 1024, DYN_BYTES>>>(
        marker, timed, maskd, emb, te_w, te_b, el_w, el_b, ml_w, ml_b,
        tl_w, tl_b, wq, wk, wv, wo, wo_b, ln1_s, ln1_b,
        ff1_w, ff1_b, ff2_w, ff2_b, ln2_s, ln2_b, out);
}